// round 10
// baseline (speedup 1.0000x reference)
#include <cuda_runtime.h>
#include <cuda_fp16.h>
#include <math.h>
#include <stdint.h>

// Problem constants
#define TT    2048
#define HH    4096
#define NHEAD 32
#define NKVH  8
#define HD    128
#define QSIZE 4096          // NHEAD*HD
#define KVSIZE 1024         // NKVH*HD
#define QKVW  6144          // QSIZE + 2*KVSIZE

// Scratch (no cudaMalloc allowed)
__device__ float  g_qkv[(size_t)TT * QKVW];      // 48 MB (fp32 qkv)
__device__ __half g_attn16[(size_t)TT * QSIZE];  // 16 MB (half attn out)
__device__ __half g_hid16[(size_t)TT * HH];      // 16 MB (half hidden)
__device__ __half g_wqkvT[(size_t)QKVW * HH];    // 48 MB (w_qkv^T half)
__device__ __half g_woT[(size_t)HH * QSIZE];     // 32 MB (w_o^T half)

// ---------------------------------------------------------------------------
// Common helpers
// ---------------------------------------------------------------------------
__device__ __forceinline__ uint32_t smem_u32(const void* p) {
    return (uint32_t)__cvta_generic_to_shared(p);
}

__device__ __forceinline__ void ldsm4(uint32_t& r0, uint32_t& r1, uint32_t& r2,
                                      uint32_t& r3, uint32_t addr) {
    asm volatile("ldmatrix.sync.aligned.m8n8.x4.shared.b16 {%0,%1,%2,%3}, [%4];"
                 : "=r"(r0), "=r"(r1), "=r"(r2), "=r"(r3) : "r"(addr));
}

__device__ __forceinline__ void ldsm4t(uint32_t& r0, uint32_t& r1, uint32_t& r2,
                                       uint32_t& r3, uint32_t addr) {
    asm volatile(
        "ldmatrix.sync.aligned.m8n8.x4.trans.shared.b16 {%0,%1,%2,%3}, [%4];"
        : "=r"(r0), "=r"(r1), "=r"(r2), "=r"(r3) : "r"(addr));
}

__device__ __forceinline__ void mma_f16(float c[4], uint32_t a0, uint32_t a1,
                                        uint32_t a2, uint32_t a3,
                                        uint32_t b0, uint32_t b1) {
    asm volatile(
        "mma.sync.aligned.m16n8k16.row.col.f32.f16.f16.f32 "
        "{%0,%1,%2,%3}, {%4,%5,%6,%7}, {%8,%9}, {%0,%1,%2,%3};"
        : "+f"(c[0]), "+f"(c[1]), "+f"(c[2]), "+f"(c[3])
        : "r"(a0), "r"(a1), "r"(a2), "r"(a3), "r"(b0), "r"(b1));
}

__device__ __forceinline__ void cpasync16(uint32_t dst, const void* src) {
    asm volatile("cp.async.cg.shared.global [%0], [%1], 16;"
                 :: "r"(dst), "l"(src));
}

// ---------------------------------------------------------------------------
// Pre-passes: fp32 -> half convert; fp32 [R][C] -> half [C][R] transpose
// ---------------------------------------------------------------------------
__global__ void conv_half(const float* __restrict__ in, __half* __restrict__ out,
                          int n4) {
    int i = blockIdx.x * blockDim.x + threadIdx.x;
    if (i >= n4) return;
    float4 v = ((const float4*)in)[i];
    __half2 h0 = __floats2half2_rn(v.x, v.y);
    __half2 h1 = __floats2half2_rn(v.z, v.w);
    ((uint2*)out)[i] = make_uint2(*(uint32_t*)&h0, *(uint32_t*)&h1);
}

__global__ void transpose_half(const float* __restrict__ in,
                               __half* __restrict__ out, int R, int C) {
    __shared__ float t[32][33];
    int tx = threadIdx.x, ty = threadIdx.y;
    int x = blockIdx.x * 32 + tx;
#pragma unroll
    for (int j = 0; j < 32; j += 8)
        t[ty + j][tx] = in[(size_t)(blockIdx.y * 32 + ty + j) * C + x];
    __syncthreads();
    int x2 = blockIdx.y * 32 + tx;
#pragma unroll
    for (int j = 0; j < 32; j += 8)
        out[(size_t)(blockIdx.x * 32 + ty + j) * R + x2] =
            __float2half_rn(t[tx][ty + j]);
}

// ---------------------------------------------------------------------------
// FP16 tensor-core GEMM, 128x256 CTA tile, 64x64 warp tile, BK=32 halves.
// C[M,N](f32) = A[M,K](h) @ Bt[N,K](h)^T ; both operands K-major.
// cp.async 4-stage pipeline, 8 warps (2m x 4n), mma.m16n8k16.
// smem rows stride 40 halves (80B): fill + all ldmatrix conflict-free.
// 1 CTA/SM (high regs) -- tensor-pipe bound by design.
// ---------------------------------------------------------------------------
#define BM 128
#define BN 256
#define HAS 40                          // halves per smem row
#define NST 4
#define STA_A (BM * HAS)                // halves per A stage
#define STA_B (BN * HAS)                // halves per B stage
#define TG_SMEM (NST * (STA_A + STA_B) * 2)   // 122880 B
#define RGROUP 8

__global__ __launch_bounds__(256, 1) void hgemm(const __half* __restrict__ A,
                                                const __half* __restrict__ Bt,
                                                float* __restrict__ C,
                                                int M, int N, int K) {
    extern __shared__ __half smh[];
    __half* As = smh;                      // [NST][BM][HAS]
    __half* Bs = smh + NST * STA_A;        // [NST][BN][HAS]

    const int tid  = threadIdx.x;
    const int lane = tid & 31;
    const int wid  = tid >> 5;
    const int mwarp = (wid >> 2) * 64;     // 0 or 64
    const int nwarp = (wid & 3) * 64;      // 0,64,128,192

    // raster swizzle: strips of RGROUP bx spanning all by
    const int flat = blockIdx.y * gridDim.x + blockIdx.x;
    const int strip = flat / (RGROUP * gridDim.y);
    const int rem   = flat % (RGROUP * gridDim.y);
    int bxg = strip * RGROUP + (rem % RGROUP);
    int byg = rem / RGROUP;
    if (bxg >= gridDim.x) { bxg = blockIdx.x; byg = blockIdx.y; }  // tail safety
    const int bx = bxg, by = byg;

    // fill mapping:
    // A: thread t -> row t/2 (0..127), two 16B chunks at halves (t&1)*16, +8
    // B: thread t -> row t (0..255), four 16B chunks at halves 0,8,16,24
    const int frow = tid >> 1;
    const int foff = (tid & 1) * 16;
    const __half* Ag = A + (size_t)(by * BM + frow) * K + foff;
    const __half* Bg = Bt + (size_t)(bx * BN + tid) * K;
    const uint32_t aDst = smem_u32(&As[frow * HAS + foff]);
    const uint32_t bDst = smem_u32(&Bs[tid * HAS]);

    const int KT = K / 32;

#define ISSUE(kt, s)                                                    \
    {                                                                   \
        const __half* a_ = Ag + (kt) * 32;                              \
        uint32_t ad_ = aDst + (s) * (STA_A * 2);                        \
        cpasync16(ad_, a_);                                             \
        cpasync16(ad_ + 16, a_ + 8);                                    \
        const __half* b_ = Bg + (kt) * 32;                              \
        uint32_t bd_ = bDst + (s) * (STA_B * 2);                        \
        cpasync16(bd_,      b_);                                        \
        cpasync16(bd_ + 16, b_ + 8);                                    \
        cpasync16(bd_ + 32, b_ + 16);                                   \
        cpasync16(bd_ + 48, b_ + 24);                                   \
        asm volatile("cp.async.commit_group;");                         \
    }

    ISSUE(0, 0);
    ISSUE(1, 1);
    ISSUE(2, 2);

    float acc[4][8][4];
#pragma unroll
    for (int mi = 0; mi < 4; mi++)
#pragma unroll
        for (int ni = 0; ni < 8; ni++)
#pragma unroll
            for (int r = 0; r < 4; r++) acc[mi][ni][r] = 0.f;

    // ldmatrix lane base addresses (bytes)
    const uint32_t aAddr =
        smem_u32(As) + ((mwarp + (lane & 15)) * HAS + (lane >> 4) * 8) * 2;
    const uint32_t bAddr =
        smem_u32(Bs) +
        ((nwarp + ((lane >> 4) << 3) + (lane & 7)) * HAS + ((lane >> 3) & 1) * 8) * 2;

    for (int kt = 0; kt < KT; kt++) {
        asm volatile("cp.async.wait_group 2;");
        __syncthreads();
        if (kt + 3 < KT) ISSUE(kt + 3, (kt + 3) % NST);

        const int s = kt % NST;
        const uint32_t aS = aAddr + s * (STA_A * 2);
        const uint32_t bS = bAddr + s * (STA_B * 2);

#pragma unroll
        for (int ks = 0; ks < 2; ks++) {
            uint32_t aF[4][4];
#pragma unroll
            for (int mi = 0; mi < 4; mi++)
                ldsm4(aF[mi][0], aF[mi][1], aF[mi][2], aF[mi][3],
                      aS + (mi * 16 * HAS + ks * 16) * 2);
            uint32_t bF[4][4];
#pragma unroll
            for (int ng = 0; ng < 4; ng++)
                ldsm4(bF[ng][0], bF[ng][1], bF[ng][2], bF[ng][3],
                      bS + (ng * 16 * HAS + ks * 16) * 2);
#pragma unroll
            for (int mi = 0; mi < 4; mi++)
#pragma unroll
                for (int ng = 0; ng < 4; ng++) {
                    mma_f16(acc[mi][ng * 2],     aF[mi][0], aF[mi][1],
                            aF[mi][2], aF[mi][3], bF[ng][0], bF[ng][1]);
                    mma_f16(acc[mi][ng * 2 + 1], aF[mi][0], aF[mi][1],
                            aF[mi][2], aF[mi][3], bF[ng][2], bF[ng][3]);
                }
        }
    }

#pragma unroll
    for (int mi = 0; mi < 4; mi++) {
#pragma unroll
        for (int ni = 0; ni < 8; ni++) {
            int r = by * BM + mwarp + mi * 16 + (lane >> 2);
            int c = bx * BN + nwarp + ni * 8 + (lane & 3) * 2;
            *(float2*)&C[(size_t)r * N + c] =
                make_float2(acc[mi][ni][0], acc[mi][ni][1]);
            *(float2*)&C[(size_t)(r + 8) * N + c] =
                make_float2(acc[mi][ni][2], acc[mi][ni][3]);
        }
    }
#undef ISSUE
}

// ---------------------------------------------------------------------------
// RoPE in-place, fp32 math
// ---------------------------------------------------------------------------
__global__ void rope_kernel(const int* __restrict__ pos, float* __restrict__ qkv) {
    const int total = TT * (NHEAD + NKVH) * 64;
    int idx = blockIdx.x * blockDim.x + threadIdx.x;
    if (idx >= total) return;
    int i = idx & 63;
    int h = (idx >> 6) % (NHEAD + NKVH);
    int t = idx / ((NHEAD + NKVH) * 64);
    int col = (h < NHEAD) ? h * HD : QSIZE + (h - NHEAD) * HD;
    float* p = qkv + (size_t)t * QKVW + col + i;
    float inv = exp2f(-(float)i * 0.2958057710522857f);
    float fr = (float)pos[t] * inv;
    float s, c;
    sincosf(fr, &s, &c);
    float x1 = p[0], x2 = p[64];
    p[0]  = x1 * c - x2 * s;
    p[64] = x2 * c + x1 * s;
}

// ---------------------------------------------------------------------------
// FP16 tensor-core flash attention (m16n8k16), causal, GQA group=4. (R9)
// ---------------------------------------------------------------------------
#define ABQ  128
#define ABKV 64
#define QSH  136    // half stride (Q,K,V rows)
#define PSH  72     // half stride (P rows)
#define ATT_SMEM ((ABQ * QSH + ABKV * QSH + ABKV * QSH + ABQ * PSH) * 2)

__global__ __launch_bounds__(256, 2) void attn_h(const float* __restrict__ qkv,
                                                 __half* __restrict__ out) {
    extern __shared__ __half ash[];
    __half* Qs = ash;                      // [128][QSH]
    __half* Ks = Qs + ABQ * QSH;           // [64][QSH]
    __half* Vs = Ks + ABKV * QSH;          // [64][QSH]
    __half* Ps = Vs + ABKV * QSH;          // [128][PSH]

    const int h  = blockIdx.x;
    const int qb = gridDim.y - 1 - blockIdx.y;   // heavy tiles first
    const int kvh = h >> 2;
    const int tid = threadIdx.x;
    const int lane = tid & 31;
    const int wid = tid >> 5;
    const int q0 = wid * 16;
    const float qsc = 0.08838834764831845f * 1.4426950408889634f;

    {
        const float* qp = qkv + (size_t)(qb * ABQ) * QKVW + h * HD;
        for (int i = tid; i < ABQ * 32; i += 256) {
            int r = i >> 5, c = (i & 31) * 4;
            float4 v = *(const float4*)(qp + (size_t)r * QKVW + c);
            __half2 h0 = __floats2half2_rn(v.x * qsc, v.y * qsc);
            __half2 h1 = __floats2half2_rn(v.z * qsc, v.w * qsc);
            *(uint2*)(Qs + r * QSH + c) =
                make_uint2(*(uint32_t*)&h0, *(uint32_t*)&h1);
        }
    }

    float m0 = -1e30f, m1 = -1e30f, l0 = 0.f, l1 = 0.f;
    float o[16][4];
#pragma unroll
    for (int ni = 0; ni < 16; ni++)
#pragma unroll
        for (int r = 0; r < 4; r++) o[ni][r] = 0.f;

    const uint32_t qA =
        smem_u32(&Qs[(q0 + (lane & 15)) * QSH + (lane >> 4) * 8]);
    const uint32_t kB =
        smem_u32(&Ks[(((lane >> 4) << 3) + (lane & 7)) * QSH + ((lane >> 3) & 1) * 8]);
    const uint32_t pA =
        smem_u32(&Ps[(q0 + (lane & 15)) * PSH + (lane >> 4) * 8]);
    const uint32_t vB =
        smem_u32(&Vs[(lane & 15) * QSH + ((lane >> 4) << 3)]);

    const int rowg0 = qb * ABQ + q0;
    const int jmax = qb * 2 + 1;

    for (int j = 0; j <= jmax; j++) {
        __syncthreads();
        {
            const float* kp = qkv + (size_t)(j * ABKV) * QKVW + QSIZE + kvh * HD;
            const float* vp = kp + KVSIZE;
            for (int i = tid; i < ABKV * 32; i += 256) {
                int r = i >> 5, c = (i & 31) * 4;
                float4 kk = *(const float4*)(kp + (size_t)r * QKVW + c);
                __half2 k0 = __floats2half2_rn(kk.x, kk.y);
                __half2 k1 = __floats2half2_rn(kk.z, kk.w);
                *(uint2*)(Ks + r * QSH + c) =
                    make_uint2(*(uint32_t*)&k0, *(uint32_t*)&k1);
                float4 vv = *(const float4*)(vp + (size_t)r * QKVW + c);
                __half2 v0 = __floats2half2_rn(vv.x, vv.y);
                __half2 v1 = __floats2half2_rn(vv.z, vv.w);
                *(uint2*)(Vs + r * QSH + c) =
                    make_uint2(*(uint32_t*)&v0, *(uint32_t*)&v1);
            }
        }
        __syncthreads();

        if (j * ABKV <= rowg0 + 15) {
            float sA[8][4];
#pragma unroll
            for (int ni = 0; ni < 8; ni++)
#pragma unroll
                for (int r = 0; r < 4; r++) sA[ni][r] = 0.f;

#pragma unroll
            for (int kc = 0; kc < 8; kc++) {
                uint32_t a[4];
                ldsm4(a[0], a[1], a[2], a[3], qA + kc * 32);
#pragma unroll
                for (int ng = 0; ng < 4; ng++) {
                    uint32_t b[4];
                    ldsm4(b[0], b[1], b[2], b[3],
                          kB + ng * (16 * QSH * 2) + kc * 32);
                    mma_f16(sA[ng * 2],     a[0], a[1], a[2], a[3], b[0], b[1]);
                    mma_f16(sA[ng * 2 + 1], a[0], a[1], a[2], a[3], b[2], b[3]);
                }
            }

            if (j * ABKV + ABKV - 1 > rowg0) {
                int rg = rowg0 + (lane >> 2);
#pragma unroll
                for (int ni = 0; ni < 8; ni++) {
                    int c0 = j * ABKV + ni * 8 + (lane & 3) * 2;
                    if (c0     > rg)     sA[ni][0] = -INFINITY;
                    if (c0 + 1 > rg)     sA[ni][1] = -INFINITY;
                    if (c0     > rg + 8) sA[ni][2] = -INFINITY;
                    if (c0 + 1 > rg + 8) sA[ni][3] = -INFINITY;
                }
            }

            float mx0 = -INFINITY, mx1 = -INFINITY;
#pragma unroll
            for (int ni = 0; ni < 8; ni++) {
                mx0 = fmaxf(mx0, fmaxf(sA[ni][0], sA[ni][1]));
                mx1 = fmaxf(mx1, fmaxf(sA[ni][2], sA[ni][3]));
            }
            mx0 = fmaxf(mx0, __shfl_xor_sync(0xffffffffu, mx0, 1));
            mx0 = fmaxf(mx0, __shfl_xor_sync(0xffffffffu, mx0, 2));
            mx1 = fmaxf(mx1, __shfl_xor_sync(0xffffffffu, mx1, 1));
            mx1 = fmaxf(mx1, __shfl_xor_sync(0xffffffffu, mx1, 2));

            float mn0 = fmaxf(m0, mx0), mn1 = fmaxf(m1, mx1);
            float cr0 = exp2f(m0 - mn0), cr1 = exp2f(m1 - mn1);
            m0 = mn0; m1 = mn1;

            float s0 = 0.f, s1 = 0.f;
            {
                int rq = q0 + (lane >> 2);
                __half* pr0 = &Ps[rq * PSH + (lane & 3) * 2];
                __half* pr1 = &Ps[(rq + 8) * PSH + (lane & 3) * 2];
#pragma unroll
                for (int ni = 0; ni < 8; ni++) {
                    float p0 = exp2f(sA[ni][0] - mn0);
                    float p1 = exp2f(sA[ni][1] - mn0);
                    float p2 = exp2f(sA[ni][2] - mn1);
                    float p3 = exp2f(sA[ni][3] - mn1);
                    s0 += p0 + p1;
                    s1 += p2 + p3;
                    *(__half2*)(pr0 + ni * 8) = __floats2half2_rn(p0, p1);
                    *(__half2*)(pr1 + ni * 8) = __floats2half2_rn(p2, p3);
                }
            }
            s0 += __shfl_xor_sync(0xffffffffu, s0, 1);
            s0 += __shfl_xor_sync(0xffffffffu, s0, 2);
            s1 += __shfl_xor_sync(0xffffffffu, s1, 1);
            s1 += __shfl_xor_sync(0xffffffffu, s1, 2);
            l0 = l0 * cr0 + s0;
            l1 = l1 * cr1 + s1;
#pragma unroll
            for (int ni = 0; ni < 16; ni++) {
                o[ni][0] *= cr0; o[ni][1] *= cr0;
                o[ni][2] *= cr1; o[ni][3] *= cr1;
            }
            __syncwarp();

#pragma unroll
            for (int sk = 0; sk < 4; sk++) {
                uint32_t a[4];
                ldsm4(a[0], a[1], a[2], a[3], pA + sk * 32);
#pragma unroll
                for (int nb = 0; nb < 8; nb++) {
                    uint32_t v[4];
                    ldsm4t(v[0], v[1], v[2], v[3],
                           vB + sk * (16 * QSH * 2) + nb * 32);
                    mma_f16(o[nb * 2],     a[0], a[1], a[2], a[3], v[0], v[1]);
                    mma_f16(o[nb * 2 + 1], a[0], a[1], a[2], a[3], v[2], v[3]);
                }
            }
            __syncwarp();
        }
    }

    float i0 = 1.f / l0, i1 = 1.f / l1;
    int rg = qb * ABQ + q0 + (lane >> 2);
    __half* op = out + (size_t)rg * QSIZE + h * HD + (lane & 3) * 2;
#pragma unroll
    for (int ni = 0; ni < 16; ni++) {
        *(__half2*)(op + ni * 8) = __floats2half2_rn(o[ni][0] * i0, o[ni][1] * i0);
        *(__half2*)(op + (size_t)8 * QSIZE + ni * 8) =
            __floats2half2_rn(o[ni][2] * i1, o[ni][3] * i1);
    }
}

// ---------------------------------------------------------------------------
extern "C" void kernel_launch(void* const* d_in, const int* in_sizes, int n_in,
                              void* d_out, int out_size) {
    const int*   positions = (const int*)d_in[0];
    const float* hidden    = (const float*)d_in[1];
    const float* w_qkv     = (const float*)d_in[2];
    const float* w_o       = (const float*)d_in[3];
    float*       out       = (float*)d_out;

    void *qkv_p, *attn_p, *hid_p, *wqkvT_p, *woT_p;
    cudaGetSymbolAddress(&qkv_p, g_qkv);
    cudaGetSymbolAddress(&attn_p, g_attn16);
    cudaGetSymbolAddress(&hid_p, g_hid16);
    cudaGetSymbolAddress(&wqkvT_p, g_wqkvT);
    cudaGetSymbolAddress(&woT_p, g_woT);
    float*  qkv    = (float*)qkv_p;
    __half* attn16 = (__half*)attn_p;
    __half* hid16  = (__half*)hid_p;
    __half* wqkvT  = (__half*)wqkvT_p;
    __half* woT    = (__half*)woT_p;

    cudaFuncSetAttribute(attn_h, cudaFuncAttributeMaxDynamicSharedMemorySize,
                         ATT_SMEM);
    cudaFuncSetAttribute(hgemm, cudaFuncAttributeMaxDynamicSharedMemorySize,
                         TG_SMEM);

    // 0) pre-passes: hidden -> half; weights -> transposed half [N][K]
    {
        int n4 = TT * HH / 4;
        conv_half<<<(n4 + 255) / 256, 256>>>(hidden, hid16, n4);
        dim3 tb(32, 8);
        transpose_half<<<dim3(QKVW / 32, HH / 32), tb>>>(w_qkv, wqkvT, HH, QKVW);
        transpose_half<<<dim3(HH / 32, QSIZE / 32), tb>>>(w_o, woT, QSIZE, HH);
    }
    // 1) qkv = hid @ w_qkv  (fp16 TC, 128x256 tiles)
    {
        dim3 grid(QKVW / BN, TT / BM);
        hgemm<<<grid, 256, TG_SMEM>>>(hid16, wqkvT, qkv, TT, QKVW, HH);
    }
    // 2) RoPE (fp32)
    {
        int total = TT * (NHEAD + NKVH) * 64;
        rope_kernel<<<(total + 255) / 256, 256>>>(positions, qkv);
    }
    // 3) attention (fp16 TC flash), half output
    {
        dim3 grid(NHEAD, TT / ABQ);
        attn_h<<<grid, 256, ATT_SMEM>>>(qkv, attn16);
    }
    // 4) out = attn @ w_o  (fp16 TC, 128x256 tiles)
    {
        dim3 grid(HH / BN, TT / BM);
        hgemm<<<grid, 256, TG_SMEM>>>(attn16, woT, out, TT, HH, QSIZE);
    }
}

// round 11
// speedup vs baseline: 1.1945x; 1.1945x over previous
#include <cuda_runtime.h>
#include <cuda_fp16.h>
#include <math.h>
#include <stdint.h>

// Problem constants
#define TT    2048
#define HH    4096
#define NHEAD 32
#define NKVH  8
#define HD    128
#define QSIZE 4096          // NHEAD*HD
#define KVSIZE 1024         // NKVH*HD
#define QKVW  6144          // QSIZE + 2*KVSIZE

// Scratch (no cudaMalloc allowed)
__device__ __half g_qkv16[(size_t)TT * QKVW];    // 24 MB (half qkv, rope applied)
__device__ __half g_attn16[(size_t)TT * QSIZE];  // 16 MB (half attn out)
__device__ __half g_hid16[(size_t)TT * HH];      // 16 MB (half hidden)
__device__ __half g_wqkvT[(size_t)QKVW * HH];    // 48 MB (w_qkv^T half)
__device__ __half g_woT[(size_t)HH * QSIZE];     // 32 MB (w_o^T half)

// ---------------------------------------------------------------------------
// Common helpers
// ---------------------------------------------------------------------------
__device__ __forceinline__ uint32_t smem_u32(const void* p) {
    return (uint32_t)__cvta_generic_to_shared(p);
}

__device__ __forceinline__ void ldsm4(uint32_t& r0, uint32_t& r1, uint32_t& r2,
                                      uint32_t& r3, uint32_t addr) {
    asm volatile("ldmatrix.sync.aligned.m8n8.x4.shared.b16 {%0,%1,%2,%3}, [%4];"
                 : "=r"(r0), "=r"(r1), "=r"(r2), "=r"(r3) : "r"(addr));
}

__device__ __forceinline__ void ldsm4t(uint32_t& r0, uint32_t& r1, uint32_t& r2,
                                       uint32_t& r3, uint32_t addr) {
    asm volatile(
        "ldmatrix.sync.aligned.m8n8.x4.trans.shared.b16 {%0,%1,%2,%3}, [%4];"
        : "=r"(r0), "=r"(r1), "=r"(r2), "=r"(r3) : "r"(addr));
}

__device__ __forceinline__ void mma_f16(float c[4], uint32_t a0, uint32_t a1,
                                        uint32_t a2, uint32_t a3,
                                        uint32_t b0, uint32_t b1) {
    asm volatile(
        "mma.sync.aligned.m16n8k16.row.col.f32.f16.f16.f32 "
        "{%0,%1,%2,%3}, {%4,%5,%6,%7}, {%8,%9}, {%0,%1,%2,%3};"
        : "+f"(c[0]), "+f"(c[1]), "+f"(c[2]), "+f"(c[3])
        : "r"(a0), "r"(a1), "r"(a2), "r"(a3), "r"(b0), "r"(b1));
}

__device__ __forceinline__ void cpasync16(uint32_t dst, const void* src) {
    asm volatile("cp.async.cg.shared.global [%0], [%1], 16;"
                 :: "r"(dst), "l"(src));
}

// ---------------------------------------------------------------------------
// Pre-passes: fp32 -> half convert; fp32 [R][C] -> half [C][R] transpose
// ---------------------------------------------------------------------------
__global__ void conv_half(const float* __restrict__ in, __half* __restrict__ out,
                          int n4) {
    int i = blockIdx.x * blockDim.x + threadIdx.x;
    if (i >= n4) return;
    float4 v = ((const float4*)in)[i];
    __half2 h0 = __floats2half2_rn(v.x, v.y);
    __half2 h1 = __floats2half2_rn(v.z, v.w);
    ((uint2*)out)[i] = make_uint2(*(uint32_t*)&h0, *(uint32_t*)&h1);
}

__global__ void transpose_half(const float* __restrict__ in,
                               __half* __restrict__ out, int R, int C) {
    __shared__ float t[32][33];
    int tx = threadIdx.x, ty = threadIdx.y;
    int x = blockIdx.x * 32 + tx;
#pragma unroll
    for (int j = 0; j < 32; j += 8)
        t[ty + j][tx] = in[(size_t)(blockIdx.y * 32 + ty + j) * C + x];
    __syncthreads();
    int x2 = blockIdx.y * 32 + tx;
#pragma unroll
    for (int j = 0; j < 32; j += 8)
        out[(size_t)(blockIdx.x * 32 + ty + j) * R + x2] =
            __float2half_rn(t[tx][ty + j]);
}

// ---------------------------------------------------------------------------
// FP16 tensor-core GEMM machinery (shared between the two GEMM kernels).
// 128x128 CTA tile, 8 warps (2m x 4n), warp tile 64x32, BK=32 halves.
// cp.async 4-stage ring, barrier every TWO kt (reads kt,kt+1 / writes kt+2,kt+3).
// smem rows stride 40 halves (80B): fill + all ldmatrix conflict-free.
// ---------------------------------------------------------------------------
#define BM 128
#define BN 128
#define HAS 40                          // halves per smem row
#define NST 4
#define STAGE_H (128 * HAS)             // halves per (A or B) stage
#define TG_SMEM (NST * 2 * STAGE_H * 2) // 81920 B
#define RGROUP 8

#define GEMM_PROLOGUE()                                                       \
    extern __shared__ __half smh[];                                           \
    __half* As = smh;                                                         \
    __half* Bs = smh + NST * STAGE_H;                                         \
    const int tid  = threadIdx.x;                                             \
    const int lane = tid & 31;                                                \
    const int wid  = tid >> 5;                                                \
    const int mwarp = (wid >> 2) * 64;                                        \
    const int nwarp = (wid & 3) * 32;                                         \
    const int flat = blockIdx.y * gridDim.x + blockIdx.x;                     \
    const int strip = flat / (RGROUP * gridDim.y);                            \
    const int rem   = flat % (RGROUP * gridDim.y);                            \
    const int bx = strip * RGROUP + (rem % RGROUP);                           \
    const int by = rem / RGROUP;                                              \
    const int frow = tid >> 1;                                                \
    const int foff = (tid & 1) * 16;                                          \
    const __half* Ag = A + (size_t)(by * BM + frow) * K + foff;               \
    const __half* Bg = Bt + (size_t)(bx * BN + frow) * K + foff;              \
    const uint32_t aDst = smem_u32(&As[frow * HAS + foff]);                   \
    const uint32_t bDst = smem_u32(&Bs[frow * HAS + foff]);                   \
    const int KT = K / 32;

#define ISSUE(kt, s)                                                          \
    {                                                                         \
        const __half* a_ = Ag + (kt) * 32;                                    \
        const __half* b_ = Bg + (kt) * 32;                                    \
        uint32_t ad_ = aDst + (s) * (STAGE_H * 2);                            \
        uint32_t bd_ = bDst + (s) * (STAGE_H * 2);                            \
        cpasync16(ad_, a_);                                                   \
        cpasync16(ad_ + 16, a_ + 8);                                          \
        cpasync16(bd_, b_);                                                   \
        cpasync16(bd_ + 16, b_ + 8);                                          \
        asm volatile("cp.async.commit_group;");                               \
    }

#define GEMM_MAINLOOP()                                                       \
    ISSUE(0, 0);                                                              \
    ISSUE(1, 1);                                                              \
    float acc[4][4][4];                                                       \
    _Pragma("unroll")                                                         \
    for (int mi = 0; mi < 4; mi++)                                            \
        _Pragma("unroll")                                                     \
        for (int ni = 0; ni < 4; ni++)                                        \
            _Pragma("unroll")                                                 \
            for (int r = 0; r < 4; r++) acc[mi][ni][r] = 0.f;                 \
    const uint32_t aAddr =                                                    \
        smem_u32(As) + ((mwarp + (lane & 15)) * HAS + (lane >> 4) * 8) * 2;   \
    const uint32_t bAddr =                                                    \
        smem_u32(Bs) +                                                        \
        ((nwarp + ((lane >> 4) << 3) + (lane & 7)) * HAS +                    \
         ((lane >> 3) & 1) * 8) * 2;                                          \
    for (int kt = 0; kt < KT; kt += 2) {                                      \
        asm volatile("cp.async.wait_group 0;");                               \
        __syncthreads();                                                      \
        if (kt + 2 < KT) {                                                    \
            ISSUE(kt + 2, (kt + 2) % NST);                                    \
            ISSUE(kt + 3, (kt + 3) % NST);                                    \
        }                                                                     \
        _Pragma("unroll")                                                     \
        for (int hf = 0; hf < 2; hf++) {                                      \
            const int s = (kt + hf) % NST;                                    \
            const uint32_t aS = aAddr + s * (STAGE_H * 2);                    \
            const uint32_t bS = bAddr + s * (STAGE_H * 2);                    \
            _Pragma("unroll")                                                 \
            for (int ks = 0; ks < 2; ks++) {                                  \
                uint32_t aF[4][4];                                            \
                _Pragma("unroll")                                             \
                for (int mi = 0; mi < 4; mi++)                                \
                    ldsm4(aF[mi][0], aF[mi][1], aF[mi][2], aF[mi][3],         \
                          aS + (mi * 16 * HAS + ks * 16) * 2);                \
                uint32_t bF[2][4];                                            \
                _Pragma("unroll")                                             \
                for (int ng = 0; ng < 2; ng++)                                \
                    ldsm4(bF[ng][0], bF[ng][1], bF[ng][2], bF[ng][3],         \
                          bS + (ng * 16 * HAS + ks * 16) * 2);                \
                _Pragma("unroll")                                             \
                for (int mi = 0; mi < 4; mi++) {                              \
                    mma_f16(acc[mi][0], aF[mi][0], aF[mi][1], aF[mi][2],      \
                            aF[mi][3], bF[0][0], bF[0][1]);                   \
                    mma_f16(acc[mi][1], aF[mi][0], aF[mi][1], aF[mi][2],      \
                            aF[mi][3], bF[0][2], bF[0][3]);                   \
                    mma_f16(acc[mi][2], aF[mi][0], aF[mi][1], aF[mi][2],      \
                            aF[mi][3], bF[1][0], bF[1][1]);                   \
                    mma_f16(acc[mi][3], aF[mi][0], aF[mi][1], aF[mi][2],      \
                            aF[mi][3], bF[1][2], bF[1][3]);                   \
                }                                                             \
            }                                                                 \
        }                                                                     \
    }

// --- GEMM2: plain fp32 output ---------------------------------------------
__global__ __launch_bounds__(256, 2) void hgemm(const __half* __restrict__ A,
                                                const __half* __restrict__ Bt,
                                                float* __restrict__ C,
                                                int M, int N, int K) {
    GEMM_PROLOGUE();
    GEMM_MAINLOOP();
#pragma unroll
    for (int mi = 0; mi < 4; mi++) {
#pragma unroll
        for (int ni = 0; ni < 4; ni++) {
            int r = by * BM + mwarp + mi * 16 + (lane >> 2);
            int c = bx * BN + nwarp + ni * 8 + (lane & 3) * 2;
            *(float2*)&C[(size_t)r * N + c] =
                make_float2(acc[mi][ni][0], acc[mi][ni][1]);
            *(float2*)&C[(size_t)(r + 8) * N + c] =
                make_float2(acc[mi][ni][2], acc[mi][ni][3]);
        }
    }
}

// --- GEMM1: rope fused in epilogue, half output ----------------------------
// BN=128 == HD, so tile bx covers exactly one head: bx<32 q, 32<=bx<40 k
// (rope applied), bx>=40 v (plain convert).
__global__ __launch_bounds__(256, 2) void hgemm_rope(
    const __half* __restrict__ A, const __half* __restrict__ Bt,
    __half* __restrict__ Cq, const int* __restrict__ pos,
    int M, int N, int K) {
    GEMM_PROLOGUE();
    GEMM_MAINLOOP();

    if (bx < 40) {
        // stage fp32 tile in (now idle) pipeline smem: [128][132] floats
        __syncthreads();
        float* Cs = (float*)smh;
#pragma unroll
        for (int mi = 0; mi < 4; mi++) {
#pragma unroll
            for (int ni = 0; ni < 4; ni++) {
                int r = mwarp + mi * 16 + (lane >> 2);
                int c = nwarp + ni * 8 + (lane & 3) * 2;
                *(float2*)&Cs[r * 132 + c] =
                    make_float2(acc[mi][ni][0], acc[mi][ni][1]);
                *(float2*)&Cs[(r + 8) * 132 + c] =
                    make_float2(acc[mi][ni][2], acc[mi][ni][3]);
            }
        }
        __syncthreads();
        const int r = tid >> 1;
        const int ibase = (tid & 1) * 32;
        const int t = by * BM + r;
        const float pf = (float)pos[t];
        __half* dst = Cq + (size_t)t * QKVW + bx * BN;
#pragma unroll 8
        for (int ii = 0; ii < 32; ii += 2) {
            int i = ibase + ii;
            float inv0 = exp2f(-(float)i * 0.2958057710522857f);
            float inv1 = exp2f(-(float)(i + 1) * 0.2958057710522857f);
            float s0, c0, s1, c1;
            sincosf(pf * inv0, &s0, &c0);
            sincosf(pf * inv1, &s1, &c1);
            float x10 = Cs[r * 132 + i],     x20 = Cs[r * 132 + i + 64];
            float x11 = Cs[r * 132 + i + 1], x21 = Cs[r * 132 + i + 65];
            *(__half2*)(dst + i) =
                __floats2half2_rn(x10 * c0 - x20 * s0, x11 * c1 - x21 * s1);
            *(__half2*)(dst + i + 64) =
                __floats2half2_rn(x20 * c0 + x10 * s0, x21 * c1 + x11 * s1);
        }
    } else {
        // V: direct half stores
#pragma unroll
        for (int mi = 0; mi < 4; mi++) {
#pragma unroll
            for (int ni = 0; ni < 4; ni++) {
                int r = by * BM + mwarp + mi * 16 + (lane >> 2);
                int c = bx * BN + nwarp + ni * 8 + (lane & 3) * 2;
                *(__half2*)&Cq[(size_t)r * QKVW + c] =
                    __floats2half2_rn(acc[mi][ni][0], acc[mi][ni][1]);
                *(__half2*)&Cq[(size_t)(r + 8) * QKVW + c] =
                    __floats2half2_rn(acc[mi][ni][2], acc[mi][ni][3]);
            }
        }
    }
}

// ---------------------------------------------------------------------------
// FP16 tensor-core flash attention (m16n8k16), causal, GQA group=4.
// Input qkv is HALF (rope already applied). Q unscaled in smem; the softmax
// scale (1/sqrt(d) * log2 e) is applied to S after the MMA.
// ---------------------------------------------------------------------------
#define ABQ  128
#define ABKV 64
#define QSH  136    // half stride (Q,K,V rows)
#define PSH  72     // half stride (P rows)
#define ATT_SMEM ((ABQ * QSH + ABKV * QSH + ABKV * QSH + ABQ * PSH) * 2)

__global__ __launch_bounds__(256, 2) void attn_h(const __half* __restrict__ qkv,
                                                 __half* __restrict__ out) {
    extern __shared__ __half ash[];
    __half* Qs = ash;                      // [128][QSH]
    __half* Ks = Qs + ABQ * QSH;           // [64][QSH]
    __half* Vs = Ks + ABKV * QSH;          // [64][QSH]
    __half* Ps = Vs + ABKV * QSH;          // [128][PSH]

    const int h  = blockIdx.x;
    const int qb = gridDim.y - 1 - blockIdx.y;   // heavy tiles first
    const int kvh = h >> 2;
    const int tid = threadIdx.x;
    const int lane = tid & 31;
    const int wid = tid >> 5;
    const int q0 = wid * 16;
    const float qsc = 0.08838834764831845f * 1.4426950408889634f;

    // ---- load Q tile (raw half copy) ----
    {
        const __half* qp = qkv + (size_t)(qb * ABQ) * QKVW + h * HD;
        for (int i = tid; i < ABQ * 32; i += 256) {
            int r = i >> 5, c = (i & 31) * 4;
            *(uint2*)(Qs + r * QSH + c) = *(const uint2*)(qp + (size_t)r * QKVW + c);
        }
    }

    float m0 = -1e30f, m1 = -1e30f, l0 = 0.f, l1 = 0.f;
    float o[16][4];
#pragma unroll
    for (int ni = 0; ni < 16; ni++)
#pragma unroll
        for (int r = 0; r < 4; r++) o[ni][r] = 0.f;

    const uint32_t qA =
        smem_u32(&Qs[(q0 + (lane & 15)) * QSH + (lane >> 4) * 8]);
    const uint32_t kB =
        smem_u32(&Ks[(((lane >> 4) << 3) + (lane & 7)) * QSH + ((lane >> 3) & 1) * 8]);
    const uint32_t pA =
        smem_u32(&Ps[(q0 + (lane & 15)) * PSH + (lane >> 4) * 8]);
    const uint32_t vB =
        smem_u32(&Vs[(lane & 15) * QSH + ((lane >> 4) << 3)]);

    const int rowg0 = qb * ABQ + q0;
    const int jmax = qb * 2 + 1;

    for (int j = 0; j <= jmax; j++) {
        __syncthreads();
        {
            const __half* kp = qkv + (size_t)(j * ABKV) * QKVW + QSIZE + kvh * HD;
            const __half* vp = kp + KVSIZE;
            for (int i = tid; i < ABKV * 32; i += 256) {
                int r = i >> 5, c = (i & 31) * 4;
                *(uint2*)(Ks + r * QSH + c) =
                    *(const uint2*)(kp + (size_t)r * QKVW + c);
                *(uint2*)(Vs + r * QSH + c) =
                    *(const uint2*)(vp + (size_t)r * QKVW + c);
            }
        }
        __syncthreads();

        if (j * ABKV <= rowg0 + 15) {
            // ---- S = Q @ K^T ----
            float sA[8][4];
#pragma unroll
            for (int ni = 0; ni < 8; ni++)
#pragma unroll
                for (int r = 0; r < 4; r++) sA[ni][r] = 0.f;

#pragma unroll
            for (int kc = 0; kc < 8; kc++) {
                uint32_t a[4];
                ldsm4(a[0], a[1], a[2], a[3], qA + kc * 32);
#pragma unroll
                for (int ng = 0; ng < 4; ng++) {
                    uint32_t b[4];
                    ldsm4(b[0], b[1], b[2], b[3],
                          kB + ng * (16 * QSH * 2) + kc * 32);
                    mma_f16(sA[ng * 2],     a[0], a[1], a[2], a[3], b[0], b[1]);
                    mma_f16(sA[ng * 2 + 1], a[0], a[1], a[2], a[3], b[2], b[3]);
                }
            }

            // ---- scale + causal mask ----
#pragma unroll
            for (int ni = 0; ni < 8; ni++)
#pragma unroll
                for (int r = 0; r < 4; r++) sA[ni][r] *= qsc;

            if (j * ABKV + ABKV - 1 > rowg0) {
                int rg = rowg0 + (lane >> 2);
#pragma unroll
                for (int ni = 0; ni < 8; ni++) {
                    int c0 = j * ABKV + ni * 8 + (lane & 3) * 2;
                    if (c0     > rg)     sA[ni][0] = -INFINITY;
                    if (c0 + 1 > rg)     sA[ni][1] = -INFINITY;
                    if (c0     > rg + 8) sA[ni][2] = -INFINITY;
                    if (c0 + 1 > rg + 8) sA[ni][3] = -INFINITY;
                }
            }

            // ---- online softmax (base 2, fp32) ----
            float mx0 = -INFINITY, mx1 = -INFINITY;
#pragma unroll
            for (int ni = 0; ni < 8; ni++) {
                mx0 = fmaxf(mx0, fmaxf(sA[ni][0], sA[ni][1]));
                mx1 = fmaxf(mx1, fmaxf(sA[ni][2], sA[ni][3]));
            }
            mx0 = fmaxf(mx0, __shfl_xor_sync(0xffffffffu, mx0, 1));
            mx0 = fmaxf(mx0, __shfl_xor_sync(0xffffffffu, mx0, 2));
            mx1 = fmaxf(mx1, __shfl_xor_sync(0xffffffffu, mx1, 1));
            mx1 = fmaxf(mx1, __shfl_xor_sync(0xffffffffu, mx1, 2));

            float mn0 = fmaxf(m0, mx0), mn1 = fmaxf(m1, mx1);
            float cr0 = exp2f(m0 - mn0), cr1 = exp2f(m1 - mn1);
            m0 = mn0; m1 = mn1;

            float s0 = 0.f, s1 = 0.f;
            {
                int rq = q0 + (lane >> 2);
                __half* pr0 = &Ps[rq * PSH + (lane & 3) * 2];
                __half* pr1 = &Ps[(rq + 8) * PSH + (lane & 3) * 2];
#pragma unroll
                for (int ni = 0; ni < 8; ni++) {
                    float p0 = exp2f(sA[ni][0] - mn0);
                    float p1 = exp2f(sA[ni][1] - mn0);
                    float p2 = exp2f(sA[ni][2] - mn1);
                    float p3 = exp2f(sA[ni][3] - mn1);
                    s0 += p0 + p1;
                    s1 += p2 + p3;
                    *(__half2*)(pr0 + ni * 8) = __floats2half2_rn(p0, p1);
                    *(__half2*)(pr1 + ni * 8) = __floats2half2_rn(p2, p3);
                }
            }
            s0 += __shfl_xor_sync(0xffffffffu, s0, 1);
            s0 += __shfl_xor_sync(0xffffffffu, s0, 2);
            s1 += __shfl_xor_sync(0xffffffffu, s1, 1);
            s1 += __shfl_xor_sync(0xffffffffu, s1, 2);
            l0 = l0 * cr0 + s0;
            l1 = l1 * cr1 + s1;
#pragma unroll
            for (int ni = 0; ni < 16; ni++) {
                o[ni][0] *= cr0; o[ni][1] *= cr0;
                o[ni][2] *= cr1; o[ni][3] *= cr1;
            }
            __syncwarp();

            // ---- O += P @ V (V via ldmatrix.trans) ----
#pragma unroll
            for (int sk = 0; sk < 4; sk++) {
                uint32_t a[4];
                ldsm4(a[0], a[1], a[2], a[3], pA + sk * 32);
#pragma unroll
                for (int nb = 0; nb < 8; nb++) {
                    uint32_t v[4];
                    ldsm4t(v[0], v[1], v[2], v[3],
                           vB + sk * (16 * QSH * 2) + nb * 32);
                    mma_f16(o[nb * 2],     a[0], a[1], a[2], a[3], v[0], v[1]);
                    mma_f16(o[nb * 2 + 1], a[0], a[1], a[2], a[3], v[2], v[3]);
                }
            }
            __syncwarp();
        }
    }

    // ---- normalize, write half (feeds fp16 GEMM2 A-side) ----
    float i0 = 1.f / l0, i1 = 1.f / l1;
    int rg = qb * ABQ + q0 + (lane >> 2);
    __half* op = out + (size_t)rg * QSIZE + h * HD + (lane & 3) * 2;
#pragma unroll
    for (int ni = 0; ni < 16; ni++) {
        *(__half2*)(op + ni * 8) = __floats2half2_rn(o[ni][0] * i0, o[ni][1] * i0);
        *(__half2*)(op + (size_t)8 * QSIZE + ni * 8) =
            __floats2half2_rn(o[ni][2] * i1, o[ni][3] * i1);
    }
}

// ---------------------------------------------------------------------------
extern "C" void kernel_launch(void* const* d_in, const int* in_sizes, int n_in,
                              void* d_out, int out_size) {
    const int*   positions = (const int*)d_in[0];
    const float* hidden    = (const float*)d_in[1];
    const float* w_qkv     = (const float*)d_in[2];
    const float* w_o       = (const float*)d_in[3];
    float*       out       = (float*)d_out;

    void *qkv_p, *attn_p, *hid_p, *wqkvT_p, *woT_p;
    cudaGetSymbolAddress(&qkv_p, g_qkv16);
    cudaGetSymbolAddress(&attn_p, g_attn16);
    cudaGetSymbolAddress(&hid_p, g_hid16);
    cudaGetSymbolAddress(&wqkvT_p, g_wqkvT);
    cudaGetSymbolAddress(&woT_p, g_woT);
    __half* qkv16  = (__half*)qkv_p;
    __half* attn16 = (__half*)attn_p;
    __half* hid16  = (__half*)hid_p;
    __half* wqkvT  = (__half*)wqkvT_p;
    __half* woT    = (__half*)woT_p;

    cudaFuncSetAttribute(attn_h, cudaFuncAttributeMaxDynamicSharedMemorySize,
                         ATT_SMEM);
    cudaFuncSetAttribute(hgemm, cudaFuncAttributeMaxDynamicSharedMemorySize,
                         TG_SMEM);
    cudaFuncSetAttribute(hgemm_rope, cudaFuncAttributeMaxDynamicSharedMemorySize,
                         TG_SMEM);

    // 0) pre-passes: hidden -> half; weights -> transposed half [N][K]
    {
        int n4 = TT * HH / 4;
        conv_half<<<(n4 + 255) / 256, 256>>>(hidden, hid16, n4);
        dim3 tb(32, 8);
        transpose_half<<<dim3(QKVW / 32, HH / 32), tb>>>(w_qkv, wqkvT, HH, QKVW);
        transpose_half<<<dim3(HH / 32, QSIZE / 32), tb>>>(w_o, woT, QSIZE, HH);
    }
    // 1) qkv(half, rope applied) = hid @ w_qkv
    {
        dim3 grid(QKVW / BN, TT / BM);
        hgemm_rope<<<grid, 256, TG_SMEM>>>(hid16, wqkvT, qkv16, positions,
                                           TT, QKVW, HH);
    }
    // 2) attention (fp16 TC flash), half in/out
    {
        dim3 grid(NHEAD, TT / ABQ);
        attn_h<<<grid, 256, ATT_SMEM>>>(qkv16, attn16);
    }
    // 3) out = attn @ w_o  (fp16 TC, fp32 out)
    {
        dim3 grid(HH / BN, TT / BM);
        hgemm<<<grid, 256, TG_SMEM>>>(attn16, woT, out, TT, HH, QSIZE);
    }
}

// round 12
// speedup vs baseline: 1.2088x; 1.0119x over previous
#include <cuda_runtime.h>
#include <cuda_fp16.h>
#include <math.h>
#include <stdint.h>

// Problem constants
#define TT    2048
#define HH    4096
#define NHEAD 32
#define NKVH  8
#define HD    128
#define QSIZE 4096          // NHEAD*HD
#define KVSIZE 1024         // NKVH*HD
#define QKVW  6144          // QSIZE + 2*KVSIZE

// Scratch (no cudaMalloc allowed)
__device__ __half g_qkv16[(size_t)TT * QKVW];    // 24 MB (half qkv, rope applied)
__device__ __half g_attn16[(size_t)TT * QSIZE];  // 16 MB (half attn out)
__device__ __half g_hid16[(size_t)TT * HH];      // 16 MB (half hidden)
__device__ __half g_wqkvT[(size_t)QKVW * HH];    // 48 MB (w_qkv^T half)
__device__ __half g_woT[(size_t)HH * QSIZE];     // 32 MB (w_o^T half)

// ---------------------------------------------------------------------------
// Common helpers
// ---------------------------------------------------------------------------
__device__ __forceinline__ uint32_t smem_u32(const void* p) {
    return (uint32_t)__cvta_generic_to_shared(p);
}

__device__ __forceinline__ void ldsm4(uint32_t& r0, uint32_t& r1, uint32_t& r2,
                                      uint32_t& r3, uint32_t addr) {
    asm volatile("ldmatrix.sync.aligned.m8n8.x4.shared.b16 {%0,%1,%2,%3}, [%4];"
                 : "=r"(r0), "=r"(r1), "=r"(r2), "=r"(r3) : "r"(addr));
}

__device__ __forceinline__ void ldsm4t(uint32_t& r0, uint32_t& r1, uint32_t& r2,
                                       uint32_t& r3, uint32_t addr) {
    asm volatile(
        "ldmatrix.sync.aligned.m8n8.x4.trans.shared.b16 {%0,%1,%2,%3}, [%4];"
        : "=r"(r0), "=r"(r1), "=r"(r2), "=r"(r3) : "r"(addr));
}

__device__ __forceinline__ void mma_f16(float c[4], uint32_t a0, uint32_t a1,
                                        uint32_t a2, uint32_t a3,
                                        uint32_t b0, uint32_t b1) {
    asm volatile(
        "mma.sync.aligned.m16n8k16.row.col.f32.f16.f16.f32 "
        "{%0,%1,%2,%3}, {%4,%5,%6,%7}, {%8,%9}, {%0,%1,%2,%3};"
        : "+f"(c[0]), "+f"(c[1]), "+f"(c[2]), "+f"(c[3])
        : "r"(a0), "r"(a1), "r"(a2), "r"(a3), "r"(b0), "r"(b1));
}

__device__ __forceinline__ void cpasync16(uint32_t dst, const void* src) {
    asm volatile("cp.async.cg.shared.global [%0], [%1], 16;"
                 :: "r"(dst), "l"(src));
}

__device__ __forceinline__ uint32_t packh2(float a, float b) {
    __half2 h = __floats2half2_rn(a, b);
    return *(uint32_t*)&h;
}

// ---------------------------------------------------------------------------
// Pre-passes: fp32 -> half convert; fp32 [R][C] -> half [C][R] transpose
// ---------------------------------------------------------------------------
__global__ void conv_half(const float* __restrict__ in, __half* __restrict__ out,
                          int n4) {
    int i = blockIdx.x * blockDim.x + threadIdx.x;
    if (i >= n4) return;
    float4 v = ((const float4*)in)[i];
    __half2 h0 = __floats2half2_rn(v.x, v.y);
    __half2 h1 = __floats2half2_rn(v.z, v.w);
    ((uint2*)out)[i] = make_uint2(*(uint32_t*)&h0, *(uint32_t*)&h1);
}

__global__ void transpose_half(const float* __restrict__ in,
                               __half* __restrict__ out, int R, int C) {
    __shared__ float t[32][33];
    int tx = threadIdx.x, ty = threadIdx.y;
    int x = blockIdx.x * 32 + tx;
#pragma unroll
    for (int j = 0; j < 32; j += 8)
        t[ty + j][tx] = in[(size_t)(blockIdx.y * 32 + ty + j) * C + x];
    __syncthreads();
    int x2 = blockIdx.y * 32 + tx;
#pragma unroll
    for (int j = 0; j < 32; j += 8)
        out[(size_t)(blockIdx.x * 32 + ty + j) * R + x2] =
            __float2half_rn(t[tx][ty + j]);
}

// ---------------------------------------------------------------------------
// FP16 tensor-core GEMM machinery (shared). 128x128 CTA tile, 8 warps,
// warp tile 64x32, BK=32 halves, cp.async 4-stage ring, barrier per 2 kt.
// (unchanged from R11)
// ---------------------------------------------------------------------------
#define BM 128
#define BN 128
#define HAS 40
#define NST 4
#define STAGE_H (128 * HAS)
#define TG_SMEM (NST * 2 * STAGE_H * 2)
#define RGROUP 8

#define GEMM_PROLOGUE()                                                       \
    extern __shared__ __half smh[];                                           \
    __half* As = smh;                                                         \
    __half* Bs = smh + NST * STAGE_H;                                         \
    const int tid  = threadIdx.x;                                             \
    const int lane = tid & 31;                                                \
    const int wid  = tid >> 5;                                                \
    const int mwarp = (wid >> 2) * 64;                                        \
    const int nwarp = (wid & 3) * 32;                                         \
    const int flat = blockIdx.y * gridDim.x + blockIdx.x;                     \
    const int strip = flat / (RGROUP * gridDim.y);                            \
    const int rem   = flat % (RGROUP * gridDim.y);                            \
    const int bx = strip * RGROUP + (rem % RGROUP);                           \
    const int by = rem / RGROUP;                                              \
    const int frow = tid >> 1;                                                \
    const int foff = (tid & 1) * 16;                                          \
    const __half* Ag = A + (size_t)(by * BM + frow) * K + foff;               \
    const __half* Bg = Bt + (size_t)(bx * BN + frow) * K + foff;              \
    const uint32_t aDst = smem_u32(&As[frow * HAS + foff]);                   \
    const uint32_t bDst = smem_u32(&Bs[frow * HAS + foff]);                   \
    const int KT = K / 32;

#define ISSUE(kt, s)                                                          \
    {                                                                         \
        const __half* a_ = Ag + (kt) * 32;                                    \
        const __half* b_ = Bg + (kt) * 32;                                    \
        uint32_t ad_ = aDst + (s) * (STAGE_H * 2);                            \
        uint32_t bd_ = bDst + (s) * (STAGE_H * 2);                            \
        cpasync16(ad_, a_);                                                   \
        cpasync16(ad_ + 16, a_ + 8);                                          \
        cpasync16(bd_, b_);                                                   \
        cpasync16(bd_ + 16, b_ + 8);                                          \
        asm volatile("cp.async.commit_group;");                               \
    }

#define GEMM_MAINLOOP()                                                       \
    ISSUE(0, 0);                                                              \
    ISSUE(1, 1);                                                              \
    float acc[4][4][4];                                                       \
    _Pragma("unroll")                                                         \
    for (int mi = 0; mi < 4; mi++)                                            \
        _Pragma("unroll")                                                     \
        for (int ni = 0; ni < 4; ni++)                                        \
            _Pragma("unroll")                                                 \
            for (int r = 0; r < 4; r++) acc[mi][ni][r] = 0.f;                 \
    const uint32_t aAddr =                                                    \
        smem_u32(As) + ((mwarp + (lane & 15)) * HAS + (lane >> 4) * 8) * 2;   \
    const uint32_t bAddr =                                                    \
        smem_u32(Bs) +                                                        \
        ((nwarp + ((lane >> 4) << 3) + (lane & 7)) * HAS +                    \
         ((lane >> 3) & 1) * 8) * 2;                                          \
    for (int kt = 0; kt < KT; kt += 2) {                                      \
        asm volatile("cp.async.wait_group 0;");                               \
        __syncthreads();                                                      \
        if (kt + 2 < KT) {                                                    \
            ISSUE(kt + 2, (kt + 2) % NST);                                    \
            ISSUE(kt + 3, (kt + 3) % NST);                                    \
        }                                                                     \
        _Pragma("unroll")                                                     \
        for (int hf = 0; hf < 2; hf++) {                                      \
            const int s = (kt + hf) % NST;                                    \
            const uint32_t aS = aAddr + s * (STAGE_H * 2);                    \
            const uint32_t bS = bAddr + s * (STAGE_H * 2);                    \
            _Pragma("unroll")                                                 \
            for (int ks = 0; ks < 2; ks++) {                                  \
                uint32_t aF[4][4];                                            \
                _Pragma("unroll")                                             \
                for (int mi = 0; mi < 4; mi++)                                \
                    ldsm4(aF[mi][0], aF[mi][1], aF[mi][2], aF[mi][3],         \
                          aS + (mi * 16 * HAS + ks * 16) * 2);                \
                uint32_t bF[2][4];                                            \
                _Pragma("unroll")                                             \
                for (int ng = 0; ng < 2; ng++)                                \
                    ldsm4(bF[ng][0], bF[ng][1], bF[ng][2], bF[ng][3],         \
                          bS + (ng * 16 * HAS + ks * 16) * 2);                \
                _Pragma("unroll")                                             \
                for (int mi = 0; mi < 4; mi++) {                              \
                    mma_f16(acc[mi][0], aF[mi][0], aF[mi][1], aF[mi][2],      \
                            aF[mi][3], bF[0][0], bF[0][1]);                   \
                    mma_f16(acc[mi][1], aF[mi][0], aF[mi][1], aF[mi][2],      \
                            aF[mi][3], bF[0][2], bF[0][3]);                   \
                    mma_f16(acc[mi][2], aF[mi][0], aF[mi][1], aF[mi][2],      \
                            aF[mi][3], bF[1][0], bF[1][1]);                   \
                    mma_f16(acc[mi][3], aF[mi][0], aF[mi][1], aF[mi][2],      \
                            aF[mi][3], bF[1][2], bF[1][3]);                   \
                }                                                             \
            }                                                                 \
        }                                                                     \
    }

// --- GEMM2: plain fp32 output ---------------------------------------------
__global__ __launch_bounds__(256, 2) void hgemm(const __half* __restrict__ A,
                                                const __half* __restrict__ Bt,
                                                float* __restrict__ C,
                                                int M, int N, int K) {
    GEMM_PROLOGUE();
    GEMM_MAINLOOP();
#pragma unroll
    for (int mi = 0; mi < 4; mi++) {
#pragma unroll
        for (int ni = 0; ni < 4; ni++) {
            int r = by * BM + mwarp + mi * 16 + (lane >> 2);
            int c = bx * BN + nwarp + ni * 8 + (lane & 3) * 2;
            *(float2*)&C[(size_t)r * N + c] =
                make_float2(acc[mi][ni][0], acc[mi][ni][1]);
            *(float2*)&C[(size_t)(r + 8) * N + c] =
                make_float2(acc[mi][ni][2], acc[mi][ni][3]);
        }
    }
}

// --- GEMM1: rope fused in epilogue, half output (unchanged R11) ------------
__global__ __launch_bounds__(256, 2) void hgemm_rope(
    const __half* __restrict__ A, const __half* __restrict__ Bt,
    __half* __restrict__ Cq, const int* __restrict__ pos,
    int M, int N, int K) {
    GEMM_PROLOGUE();
    GEMM_MAINLOOP();

    if (bx < 40) {
        __syncthreads();
        float* Cs = (float*)smh;
#pragma unroll
        for (int mi = 0; mi < 4; mi++) {
#pragma unroll
            for (int ni = 0; ni < 4; ni++) {
                int r = mwarp + mi * 16 + (lane >> 2);
                int c = nwarp + ni * 8 + (lane & 3) * 2;
                *(float2*)&Cs[r * 132 + c] =
                    make_float2(acc[mi][ni][0], acc[mi][ni][1]);
                *(float2*)&Cs[(r + 8) * 132 + c] =
                    make_float2(acc[mi][ni][2], acc[mi][ni][3]);
            }
        }
        __syncthreads();
        const int r = tid >> 1;
        const int ibase = (tid & 1) * 32;
        const int t = by * BM + r;
        const float pf = (float)pos[t];
        __half* dst = Cq + (size_t)t * QKVW + bx * BN;
#pragma unroll 8
        for (int ii = 0; ii < 32; ii += 2) {
            int i = ibase + ii;
            float inv0 = exp2f(-(float)i * 0.2958057710522857f);
            float inv1 = exp2f(-(float)(i + 1) * 0.2958057710522857f);
            float s0, c0, s1, c1;
            sincosf(pf * inv0, &s0, &c0);
            sincosf(pf * inv1, &s1, &c1);
            float x10 = Cs[r * 132 + i],     x20 = Cs[r * 132 + i + 64];
            float x11 = Cs[r * 132 + i + 1], x21 = Cs[r * 132 + i + 65];
            *(__half2*)(dst + i) =
                __floats2half2_rn(x10 * c0 - x20 * s0, x11 * c1 - x21 * s1);
            *(__half2*)(dst + i + 64) =
                __floats2half2_rn(x20 * c0 + x10 * s0, x21 * c1 + x11 * s1);
        }
    } else {
#pragma unroll
        for (int mi = 0; mi < 4; mi++) {
#pragma unroll
            for (int ni = 0; ni < 4; ni++) {
                int r = by * BM + mwarp + mi * 16 + (lane >> 2);
                int c = bx * BN + nwarp + ni * 8 + (lane & 3) * 2;
                *(__half2*)&Cq[(size_t)r * QKVW + c] =
                    __floats2half2_rn(acc[mi][ni][0], acc[mi][ni][1]);
                *(__half2*)&Cq[(size_t)(r + 8) * QKVW + c] =
                    __floats2half2_rn(acc[mi][ni][2], acc[mi][ni][3]);
            }
        }
    }
}

// ---------------------------------------------------------------------------
// FP16 flash attention (m16n8k16), causal, GQA group=4.
// R12: P kept in registers (S c-frag == P a-frag layout); K/V double-buffered
// via cp.async (raw half copies). Q unscaled; scale*log2e applied to S.
// smem: Q[128][136] + 2 stages of (K[64][136] + V[64][136]) = 104448 B.
// ---------------------------------------------------------------------------
#define ABQ  128
#define ABKV 64
#define QSH  136                       // half stride
#define Q_HALVES (ABQ * QSH)           // 17408
#define KV_STAGE_HALVES (2 * ABKV * QSH)  // 17408 (K + V)
#define ATT_SMEM ((Q_HALVES + 2 * KV_STAGE_HALVES) * 2)   // 104448 B

__global__ __launch_bounds__(256, 2) void attn_h(const __half* __restrict__ qkv,
                                                 __half* __restrict__ out) {
    extern __shared__ __half ash[];
    __half* Qs = ash;                                  // [128][QSH]

    const int h  = blockIdx.x;
    const int qb = gridDim.y - 1 - blockIdx.y;         // heavy tiles first
    const int kvh = h >> 2;
    const int tid = threadIdx.x;
    const int lane = tid & 31;
    const int wid = tid >> 5;
    const int q0 = wid * 16;
    const float qsc = 0.08838834764831845f * 1.4426950408889634f;

    const __half* kgbase = qkv + QSIZE + kvh * HD;
    const __half* vgbase = kgbase + KVSIZE;

    // stage fill: 64 rows x 16 chunks (16B) for K and V each; 8 chunks/thread
    const uint32_t smBase = smem_u32(ash);
#define KV_ISSUE(j, s)                                                        \
    {                                                                         \
        const __half* kg_ = kgbase + (size_t)((j) * ABKV) * QKVW;             \
        const __half* vg_ = vgbase + (size_t)((j) * ABKV) * QKVW;             \
        uint32_t kb_ = smBase + (Q_HALVES + (s) * KV_STAGE_HALVES) * 2;       \
        uint32_t vb_ = kb_ + ABKV * QSH * 2;                                  \
        _Pragma("unroll")                                                     \
        for (int i_ = 0; i_ < 4; i_++) {                                      \
            int idx_ = i_ * 256 + tid;                                        \
            int r_ = idx_ >> 4, ck_ = (idx_ & 15) * 8;                        \
            uint32_t off_ = (r_ * QSH + ck_) * 2;                             \
            cpasync16(kb_ + off_, kg_ + (size_t)r_ * QKVW + ck_);             \
            cpasync16(vb_ + off_, vg_ + (size_t)r_ * QKVW + ck_);             \
        }                                                                     \
        asm volatile("cp.async.commit_group;");                               \
    }

    // Q tile (cp.async too; lands with stage 0's group)
    {
        const __half* qp = qkv + (size_t)(qb * ABQ) * QKVW + h * HD;
#pragma unroll
        for (int i = 0; i < 8; i++) {
            int idx = i * 256 + tid;
            int r = idx >> 4, ck = (idx & 15) * 8;
            cpasync16(smBase + (r * QSH + ck) * 2,
                      qp + (size_t)r * QKVW + ck);
        }
    }
    KV_ISSUE(0, 0);

    float m0 = -1e30f, m1 = -1e30f, l0 = 0.f, l1 = 0.f;
    float o[16][4];
#pragma unroll
    for (int ni = 0; ni < 16; ni++)
#pragma unroll
        for (int r = 0; r < 4; r++) o[ni][r] = 0.f;

    const uint32_t qA =
        smBase + ((q0 + (lane & 15)) * QSH + (lane >> 4) * 8) * 2;
    const uint32_t kOff =
        (((((lane >> 4) << 3) + (lane & 7)) * QSH + ((lane >> 3) & 1) * 8)) * 2;
    const uint32_t vOff = ((lane & 15) * QSH + ((lane >> 4) << 3)) * 2;

    const int rowg0 = qb * ABQ + q0;
    const int jmax = qb * 2 + 1;

    for (int j = 0; j <= jmax; j++) {
        asm volatile("cp.async.wait_group 0;");
        __syncthreads();
        if (j + 1 <= jmax) KV_ISSUE(j + 1, (j + 1) & 1);

        const uint32_t stBase =
            smBase + (Q_HALVES + (j & 1) * KV_STAGE_HALVES) * 2;
        const uint32_t kB = stBase + kOff;
        const uint32_t vB = stBase + ABKV * QSH * 2 + vOff;

        if (j * ABKV <= rowg0 + 15) {
            // ---- S = Q @ K^T ----
            float sA[8][4];
#pragma unroll
            for (int ni = 0; ni < 8; ni++)
#pragma unroll
                for (int r = 0; r < 4; r++) sA[ni][r] = 0.f;

#pragma unroll
            for (int kc = 0; kc < 8; kc++) {
                uint32_t a[4];
                ldsm4(a[0], a[1], a[2], a[3], qA + kc * 32);
#pragma unroll
                for (int ng = 0; ng < 4; ng++) {
                    uint32_t b[4];
                    ldsm4(b[0], b[1], b[2], b[3],
                          kB + ng * (16 * QSH * 2) + kc * 32);
                    mma_f16(sA[ng * 2],     a[0], a[1], a[2], a[3], b[0], b[1]);
                    mma_f16(sA[ng * 2 + 1], a[0], a[1], a[2], a[3], b[2], b[3]);
                }
            }

            // ---- scale + causal mask ----
#pragma unroll
            for (int ni = 0; ni < 8; ni++)
#pragma unroll
                for (int r = 0; r < 4; r++) sA[ni][r] *= qsc;

            if (j * ABKV + ABKV - 1 > rowg0) {
                int rg = rowg0 + (lane >> 2);
#pragma unroll
                for (int ni = 0; ni < 8; ni++) {
                    int c0 = j * ABKV + ni * 8 + (lane & 3) * 2;
                    if (c0     > rg)     sA[ni][0] = -INFINITY;
                    if (c0 + 1 > rg)     sA[ni][1] = -INFINITY;
                    if (c0     > rg + 8) sA[ni][2] = -INFINITY;
                    if (c0 + 1 > rg + 8) sA[ni][3] = -INFINITY;
                }
            }

            // ---- online softmax (base 2, fp32) ----
            float mx0 = -INFINITY, mx1 = -INFINITY;
#pragma unroll
            for (int ni = 0; ni < 8; ni++) {
                mx0 = fmaxf(mx0, fmaxf(sA[ni][0], sA[ni][1]));
                mx1 = fmaxf(mx1, fmaxf(sA[ni][2], sA[ni][3]));
            }
            mx0 = fmaxf(mx0, __shfl_xor_sync(0xffffffffu, mx0, 1));
            mx0 = fmaxf(mx0, __shfl_xor_sync(0xffffffffu, mx0, 2));
            mx1 = fmaxf(mx1, __shfl_xor_sync(0xffffffffu, mx1, 1));
            mx1 = fmaxf(mx1, __shfl_xor_sync(0xffffffffu, mx1, 2));

            float mn0 = fmaxf(m0, mx0), mn1 = fmaxf(m1, mx1);
            float cr0 = exp2f(m0 - mn0), cr1 = exp2f(m1 - mn1);
            m0 = mn0; m1 = mn1;

            float s0 = 0.f, s1 = 0.f;
            uint32_t pF[4][4];   // P as A-fragments: chunk sk covers s=16sk..+15
#pragma unroll
            for (int sk = 0; sk < 4; sk++) {
                float p00 = exp2f(sA[2 * sk][0] - mn0);
                float p01 = exp2f(sA[2 * sk][1] - mn0);
                float p02 = exp2f(sA[2 * sk][2] - mn1);
                float p03 = exp2f(sA[2 * sk][3] - mn1);
                float p10 = exp2f(sA[2 * sk + 1][0] - mn0);
                float p11 = exp2f(sA[2 * sk + 1][1] - mn0);
                float p12 = exp2f(sA[2 * sk + 1][2] - mn1);
                float p13 = exp2f(sA[2 * sk + 1][3] - mn1);
                s0 += p00 + p01 + p10 + p11;
                s1 += p02 + p03 + p12 + p13;
                pF[sk][0] = packh2(p00, p01);   // rows lane>>2,   k-lo
                pF[sk][1] = packh2(p02, p03);   // rows +8,        k-lo
                pF[sk][2] = packh2(p10, p11);   // rows lane>>2,   k-hi
                pF[sk][3] = packh2(p12, p13);   // rows +8,        k-hi
            }
            s0 += __shfl_xor_sync(0xffffffffu, s0, 1);
            s0 += __shfl_xor_sync(0xffffffffu, s0, 2);
            s1 += __shfl_xor_sync(0xffffffffu, s1, 1);
            s1 += __shfl_xor_sync(0xffffffffu, s1, 2);
            l0 = l0 * cr0 + s0;
            l1 = l1 * cr1 + s1;
#pragma unroll
            for (int ni = 0; ni < 16; ni++) {
                o[ni][0] *= cr0; o[ni][1] *= cr0;
                o[ni][2] *= cr1; o[ni][3] *= cr1;
            }

            // ---- O += P @ V (P from registers, V via ldmatrix.trans) ----
#pragma unroll
            for (int sk = 0; sk < 4; sk++) {
#pragma unroll
                for (int nb = 0; nb < 8; nb++) {
                    uint32_t v[4];
                    ldsm4t(v[0], v[1], v[2], v[3],
                           vB + sk * (16 * QSH * 2) + nb * 32);
                    mma_f16(o[nb * 2], pF[sk][0], pF[sk][1], pF[sk][2],
                            pF[sk][3], v[0], v[1]);
                    mma_f16(o[nb * 2 + 1], pF[sk][0], pF[sk][1], pF[sk][2],
                            pF[sk][3], v[2], v[3]);
                }
            }
        }
    }

    // ---- normalize, write half (feeds fp16 GEMM2 A-side) ----
    float i0 = 1.f / l0, i1 = 1.f / l1;
    int rg = qb * ABQ + q0 + (lane >> 2);
    __half* op = out + (size_t)rg * QSIZE + h * HD + (lane & 3) * 2;
#pragma unroll
    for (int ni = 0; ni < 16; ni++) {
        *(__half2*)(op + ni * 8) = __floats2half2_rn(o[ni][0] * i0, o[ni][1] * i0);
        *(__half2*)(op + (size_t)8 * QSIZE + ni * 8) =
            __floats2half2_rn(o[ni][2] * i1, o[ni][3] * i1);
    }
#undef KV_ISSUE
}

// ---------------------------------------------------------------------------
extern "C" void kernel_launch(void* const* d_in, const int* in_sizes, int n_in,
                              void* d_out, int out_size) {
    const int*   positions = (const int*)d_in[0];
    const float* hidden    = (const float*)d_in[1];
    const float* w_qkv     = (const float*)d_in[2];
    const float* w_o       = (const float*)d_in[3];
    float*       out       = (float*)d_out;

    void *qkv_p, *attn_p, *hid_p, *wqkvT_p, *woT_p;
    cudaGetSymbolAddress(&qkv_p, g_qkv16);
    cudaGetSymbolAddress(&attn_p, g_attn16);
    cudaGetSymbolAddress(&hid_p, g_hid16);
    cudaGetSymbolAddress(&wqkvT_p, g_wqkvT);
    cudaGetSymbolAddress(&woT_p, g_woT);
    __half* qkv16  = (__half*)qkv_p;
    __half* attn16 = (__half*)attn_p;
    __half* hid16  = (__half*)hid_p;
    __half* wqkvT  = (__half*)wqkvT_p;
    __half* woT    = (__half*)woT_p;

    cudaFuncSetAttribute(attn_h, cudaFuncAttributeMaxDynamicSharedMemorySize,
                         ATT_SMEM);
    cudaFuncSetAttribute(hgemm, cudaFuncAttributeMaxDynamicSharedMemorySize,
                         TG_SMEM);
    cudaFuncSetAttribute(hgemm_rope, cudaFuncAttributeMaxDynamicSharedMemorySize,
                         TG_SMEM);

    // 0) pre-passes: hidden -> half; weights -> transposed half [N][K]
    {
        int n4 = TT * HH / 4;
        conv_half<<<(n4 + 255) / 256, 256>>>(hidden, hid16, n4);
        dim3 tb(32, 8);
        transpose_half<<<dim3(QKVW / 32, HH / 32), tb>>>(w_qkv, wqkvT, HH, QKVW);
        transpose_half<<<dim3(HH / 32, QSIZE / 32), tb>>>(w_o, woT, QSIZE, HH);
    }
    // 1) qkv(half, rope applied) = hid @ w_qkv
    {
        dim3 grid(QKVW / BN, TT / BM);
        hgemm_rope<<<grid, 256, TG_SMEM>>>(hid16, wqkvT, qkv16, positions,
                                           TT, QKVW, HH);
    }
    // 2) attention (fp16 TC flash), half in/out
    {
        dim3 grid(NHEAD, TT / ABQ);
        attn_h<<<grid, 256, ATT_SMEM>>>(qkv16, attn16);
    }
    // 3) out = attn @ w_o  (fp16 TC, fp32 out)
    {
        dim3 grid(HH / BN, TT / BM);
        hgemm<<<grid, 256, TG_SMEM>>>(attn16, woT, out, TT, HH, QSIZE);
    }
}

// round 13
// speedup vs baseline: 1.4298x; 1.1828x over previous
#include <cuda_runtime.h>
#include <cuda_fp16.h>
#include <math.h>
#include <stdint.h>

// Problem constants
#define TT    2048
#define HH    4096
#define NHEAD 32
#define NKVH  8
#define HD    128
#define QSIZE 4096          // NHEAD*HD
#define KVSIZE 1024         // NKVH*HD
#define QKVW  6144          // QSIZE + 2*KVSIZE

// Scratch (no cudaMalloc allowed)
__device__ __half g_qkv16[(size_t)TT * QKVW];    // 24 MB (half qkv, rope applied)
__device__ __half g_attn16[(size_t)TT * QSIZE];  // 16 MB (half attn out)
__device__ __half g_hid16[(size_t)TT * HH];      // 16 MB (half hidden)
__device__ __half g_wqkvT[(size_t)QKVW * HH];    // 48 MB (w_qkv^T half)
__device__ __half g_woT[(size_t)HH * QSIZE];     // 32 MB (w_o^T half)

// ---------------------------------------------------------------------------
// Common helpers
// ---------------------------------------------------------------------------
__device__ __forceinline__ uint32_t smem_u32(const void* p) {
    return (uint32_t)__cvta_generic_to_shared(p);
}

__device__ __forceinline__ void ldsm4(uint32_t& r0, uint32_t& r1, uint32_t& r2,
                                      uint32_t& r3, uint32_t addr) {
    asm volatile("ldmatrix.sync.aligned.m8n8.x4.shared.b16 {%0,%1,%2,%3}, [%4];"
                 : "=r"(r0), "=r"(r1), "=r"(r2), "=r"(r3) : "r"(addr));
}

__device__ __forceinline__ void ldsm4t(uint32_t& r0, uint32_t& r1, uint32_t& r2,
                                       uint32_t& r3, uint32_t addr) {
    asm volatile(
        "ldmatrix.sync.aligned.m8n8.x4.trans.shared.b16 {%0,%1,%2,%3}, [%4];"
        : "=r"(r0), "=r"(r1), "=r"(r2), "=r"(r3) : "r"(addr));
}

__device__ __forceinline__ void mma_f16(float c[4], uint32_t a0, uint32_t a1,
                                        uint32_t a2, uint32_t a3,
                                        uint32_t b0, uint32_t b1) {
    asm volatile(
        "mma.sync.aligned.m16n8k16.row.col.f32.f16.f16.f32 "
        "{%0,%1,%2,%3}, {%4,%5,%6,%7}, {%8,%9}, {%0,%1,%2,%3};"
        : "+f"(c[0]), "+f"(c[1]), "+f"(c[2]), "+f"(c[3])
        : "r"(a0), "r"(a1), "r"(a2), "r"(a3), "r"(b0), "r"(b1));
}

__device__ __forceinline__ void cpasync16(uint32_t dst, const void* src) {
    asm volatile("cp.async.cg.shared.global [%0], [%1], 16;"
                 :: "r"(dst), "l"(src));
}

__device__ __forceinline__ uint32_t packh2(float a, float b) {
    __half2 h = __floats2half2_rn(a, b);
    return *(uint32_t*)&h;
}

__device__ __forceinline__ void mbar_init(uint32_t mbar, uint32_t cnt) {
    asm volatile("mbarrier.init.shared.b64 [%0], %1;" :: "r"(mbar), "r"(cnt)
                 : "memory");
}

__device__ __forceinline__ void mbar_arrive(uint32_t mbar) {
    asm volatile("mbarrier.arrive.shared.b64 _, [%0];" :: "r"(mbar) : "memory");
}

__device__ __forceinline__ void cp_arrive_noinc(uint32_t mbar) {
    asm volatile("cp.async.mbarrier.arrive.noinc.shared.b64 [%0];"
                 :: "r"(mbar) : "memory");
}

__device__ __forceinline__ void mbar_wait(uint32_t mbar, uint32_t phase) {
    asm volatile(
        "{\n\t.reg .pred P;\n"
        "W%=:\n\t"
        "mbarrier.try_wait.parity.acquire.cta.shared::cta.b64 P, [%0], %1, 0x989680;\n\t"
        "@P bra D%=;\n\t"
        "bra W%=;\n"
        "D%=:\n\t}"
        :: "r"(mbar), "r"(phase) : "memory");
}

// ---------------------------------------------------------------------------
// Pre-passes: fp32 -> half convert; fp32 [R][C] -> half [C][R] transpose
// ---------------------------------------------------------------------------
__global__ void conv_half(const float* __restrict__ in, __half* __restrict__ out,
                          int n4) {
    int i = blockIdx.x * blockDim.x + threadIdx.x;
    if (i >= n4) return;
    float4 v = ((const float4*)in)[i];
    __half2 h0 = __floats2half2_rn(v.x, v.y);
    __half2 h1 = __floats2half2_rn(v.z, v.w);
    ((uint2*)out)[i] = make_uint2(*(uint32_t*)&h0, *(uint32_t*)&h1);
}

__global__ void transpose_half(const float* __restrict__ in,
                               __half* __restrict__ out, int R, int C) {
    __shared__ float t[32][33];
    int tx = threadIdx.x, ty = threadIdx.y;
    int x = blockIdx.x * 32 + tx;
#pragma unroll
    for (int j = 0; j < 32; j += 8)
        t[ty + j][tx] = in[(size_t)(blockIdx.y * 32 + ty + j) * C + x];
    __syncthreads();
    int x2 = blockIdx.y * 32 + tx;
#pragma unroll
    for (int j = 0; j < 32; j += 8)
        out[(size_t)(blockIdx.x * 32 + ty + j) * R + x2] =
            __float2half_rn(t[tx][ty + j]);
}

// ---------------------------------------------------------------------------
// FP16 tensor-core GEMM, barrier-free elastic pipeline (mbarrier full/empty).
// 128x128 CTA tile, 8 warps (2m x 4n), warp tile 64x32, BK=32 halves, 4 stages.
// full[s]: count 256, armed via per-thread cp.async.mbarrier.arrive.noinc.
// empty[s]: count 8, elected per-warp arrive after the warp consumed stage s.
// Warps run free; no __syncthreads in the mainloop.
// ---------------------------------------------------------------------------
#define BM 128
#define BN 128
#define HAS 40
#define NST 4
#define STAGE_H (128 * HAS)
#define TG_SMEM (NST * 2 * STAGE_H * 2)
#define RGROUP 8

#define GEMM_PROLOGUE()                                                       \
    extern __shared__ __half smh[];                                           \
    __shared__ __align__(8) uint64_t s_full[NST];                             \
    __shared__ __align__(8) uint64_t s_empty[NST];                            \
    __half* As = smh;                                                         \
    __half* Bs = smh + NST * STAGE_H;                                         \
    const int tid  = threadIdx.x;                                             \
    const int lane = tid & 31;                                                \
    const int wid  = tid >> 5;                                                \
    const int mwarp = (wid >> 2) * 64;                                        \
    const int nwarp = (wid & 3) * 32;                                         \
    const int flat = blockIdx.y * gridDim.x + blockIdx.x;                     \
    const int strip = flat / (RGROUP * gridDim.y);                            \
    const int rem   = flat % (RGROUP * gridDim.y);                            \
    const int bx = strip * RGROUP + (rem % RGROUP);                           \
    const int by = rem / RGROUP;                                              \
    const int frow = tid >> 1;                                                \
    const int foff = (tid & 1) * 16;                                          \
    const __half* Ag = A + (size_t)(by * BM + frow) * K + foff;               \
    const __half* Bg = Bt + (size_t)(bx * BN + frow) * K + foff;              \
    const uint32_t aDst = smem_u32(&As[frow * HAS + foff]);                   \
    const uint32_t bDst = smem_u32(&Bs[frow * HAS + foff]);                   \
    const uint32_t mbF = smem_u32(s_full);                                    \
    const uint32_t mbE = smem_u32(s_empty);                                   \
    const int KT = K / 32;                                                    \
    if (tid == 0) {                                                           \
        for (int s_ = 0; s_ < NST; s_++) {                                    \
            mbar_init(mbF + s_ * 8, 256u);                                    \
            mbar_init(mbE + s_ * 8, 8u);                                      \
        }                                                                     \
    }                                                                         \
    __syncthreads();

#define ISSUE(kt, s)                                                          \
    {                                                                         \
        const __half* a_ = Ag + (kt) * 32;                                    \
        const __half* b_ = Bg + (kt) * 32;                                    \
        uint32_t ad_ = aDst + (s) * (STAGE_H * 2);                            \
        uint32_t bd_ = bDst + (s) * (STAGE_H * 2);                            \
        cpasync16(ad_, a_);                                                   \
        cpasync16(ad_ + 16, a_ + 8);                                          \
        cpasync16(bd_, b_);                                                   \
        cpasync16(bd_ + 16, b_ + 8);                                          \
        cp_arrive_noinc(mbF + (s) * 8);                                       \
    }

#define GEMM_MAINLOOP()                                                       \
    ISSUE(0, 0);                                                              \
    ISSUE(1, 1);                                                              \
    float acc[4][4][4];                                                       \
    _Pragma("unroll")                                                         \
    for (int mi = 0; mi < 4; mi++)                                            \
        _Pragma("unroll")                                                     \
        for (int ni = 0; ni < 4; ni++)                                        \
            _Pragma("unroll")                                                 \
            for (int r = 0; r < 4; r++) acc[mi][ni][r] = 0.f;                 \
    const uint32_t aAddr =                                                    \
        smem_u32(As) + ((mwarp + (lane & 15)) * HAS + (lane >> 4) * 8) * 2;   \
    const uint32_t bAddr =                                                    \
        smem_u32(Bs) +                                                        \
        ((nwarp + ((lane >> 4) << 3) + (lane & 7)) * HAS +                    \
         ((lane >> 3) & 1) * 8) * 2;                                          \
    for (int kt = 0; kt < KT; kt++) {                                         \
        const int fkt = kt + 2;                                               \
        if (fkt < KT) {                                                       \
            const int fs = fkt & (NST - 1);                                   \
            if (fkt >= NST)                                                   \
                mbar_wait(mbE + fs * 8, ((fkt >> 2) + 1) & 1);                \
            ISSUE(fkt, fs);                                                   \
        }                                                                     \
        const int s = kt & (NST - 1);                                         \
        mbar_wait(mbF + s * 8, (kt >> 2) & 1);                                \
        const uint32_t aS = aAddr + s * (STAGE_H * 2);                        \
        const uint32_t bS = bAddr + s * (STAGE_H * 2);                        \
        _Pragma("unroll")                                                     \
        for (int ks = 0; ks < 2; ks++) {                                      \
            uint32_t aF[4][4];                                                \
            _Pragma("unroll")                                                 \
            for (int mi = 0; mi < 4; mi++)                                    \
                ldsm4(aF[mi][0], aF[mi][1], aF[mi][2], aF[mi][3],             \
                      aS + (mi * 16 * HAS + ks * 16) * 2);                    \
            uint32_t bF[2][4];                                                \
            _Pragma("unroll")                                                 \
            for (int ng = 0; ng < 2; ng++)                                    \
                ldsm4(bF[ng][0], bF[ng][1], bF[ng][2], bF[ng][3],             \
                      bS + (ng * 16 * HAS + ks * 16) * 2);                    \
            _Pragma("unroll")                                                 \
            for (int mi = 0; mi < 4; mi++) {                                  \
                mma_f16(acc[mi][0], aF[mi][0], aF[mi][1], aF[mi][2],          \
                        aF[mi][3], bF[0][0], bF[0][1]);                       \
                mma_f16(acc[mi][1], aF[mi][0], aF[mi][1], aF[mi][2],          \
                        aF[mi][3], bF[0][2], bF[0][3]);                       \
                mma_f16(acc[mi][2], aF[mi][0], aF[mi][1], aF[mi][2],          \
                        aF[mi][3], bF[1][0], bF[1][1]);                       \
                mma_f16(acc[mi][3], aF[mi][0], aF[mi][1], aF[mi][2],          \
                        aF[mi][3], bF[1][2], bF[1][3]);                       \
            }                                                                 \
        }                                                                     \
        __syncwarp();                                                         \
        if (lane == 0) mbar_arrive(mbE + s * 8);                              \
    }

// --- GEMM2: plain fp32 output ---------------------------------------------
__global__ __launch_bounds__(256, 2) void hgemm(const __half* __restrict__ A,
                                                const __half* __restrict__ Bt,
                                                float* __restrict__ C,
                                                int M, int N, int K) {
    GEMM_PROLOGUE();
    GEMM_MAINLOOP();
#pragma unroll
    for (int mi = 0; mi < 4; mi++) {
#pragma unroll
        for (int ni = 0; ni < 4; ni++) {
            int r = by * BM + mwarp + mi * 16 + (lane >> 2);
            int c = bx * BN + nwarp + ni * 8 + (lane & 3) * 2;
            *(float2*)&C[(size_t)r * N + c] =
                make_float2(acc[mi][ni][0], acc[mi][ni][1]);
            *(float2*)&C[(size_t)(r + 8) * N + c] =
                make_float2(acc[mi][ni][2], acc[mi][ni][3]);
        }
    }
}

// --- GEMM1: rope fused in epilogue, half output ----------------------------
__global__ __launch_bounds__(256, 2) void hgemm_rope(
    const __half* __restrict__ A, const __half* __restrict__ Bt,
    __half* __restrict__ Cq, const int* __restrict__ pos,
    int M, int N, int K) {
    GEMM_PROLOGUE();
    GEMM_MAINLOOP();

    if (bx < 40) {
        __syncthreads();      // all warps done with pipeline smem
        float* Cs = (float*)smh;
#pragma unroll
        for (int mi = 0; mi < 4; mi++) {
#pragma unroll
            for (int ni = 0; ni < 4; ni++) {
                int r = mwarp + mi * 16 + (lane >> 2);
                int c = nwarp + ni * 8 + (lane & 3) * 2;
                *(float2*)&Cs[r * 132 + c] =
                    make_float2(acc[mi][ni][0], acc[mi][ni][1]);
                *(float2*)&Cs[(r + 8) * 132 + c] =
                    make_float2(acc[mi][ni][2], acc[mi][ni][3]);
            }
        }
        __syncthreads();
        const int r = tid >> 1;
        const int ibase = (tid & 1) * 32;
        const int t = by * BM + r;
        const float pf = (float)pos[t];
        __half* dst = Cq + (size_t)t * QKVW + bx * BN;
#pragma unroll 8
        for (int ii = 0; ii < 32; ii += 2) {
            int i = ibase + ii;
            float inv0 = exp2f(-(float)i * 0.2958057710522857f);
            float inv1 = exp2f(-(float)(i + 1) * 0.2958057710522857f);
            float s0, c0, s1, c1;
            sincosf(pf * inv0, &s0, &c0);
            sincosf(pf * inv1, &s1, &c1);
            float x10 = Cs[r * 132 + i],     x20 = Cs[r * 132 + i + 64];
            float x11 = Cs[r * 132 + i + 1], x21 = Cs[r * 132 + i + 65];
            *(__half2*)(dst + i) =
                __floats2half2_rn(x10 * c0 - x20 * s0, x11 * c1 - x21 * s1);
            *(__half2*)(dst + i + 64) =
                __floats2half2_rn(x20 * c0 + x10 * s0, x21 * c1 + x11 * s1);
        }
    } else {
#pragma unroll
        for (int mi = 0; mi < 4; mi++) {
#pragma unroll
            for (int ni = 0; ni < 4; ni++) {
                int r = by * BM + mwarp + mi * 16 + (lane >> 2);
                int c = bx * BN + nwarp + ni * 8 + (lane & 3) * 2;
                *(__half2*)&Cq[(size_t)r * QKVW + c] =
                    __floats2half2_rn(acc[mi][ni][0], acc[mi][ni][1]);
                *(__half2*)&Cq[(size_t)(r + 8) * QKVW + c] =
                    __floats2half2_rn(acc[mi][ni][2], acc[mi][ni][3]);
            }
        }
    }
}

// ---------------------------------------------------------------------------
// FP16 flash attention (m16n8k16), causal, GQA group=4. (unchanged R12)
// ---------------------------------------------------------------------------
#define ABQ  128
#define ABKV 64
#define QSH  136
#define Q_HALVES (ABQ * QSH)
#define KV_STAGE_HALVES (2 * ABKV * QSH)
#define ATT_SMEM ((Q_HALVES + 2 * KV_STAGE_HALVES) * 2)

__global__ __launch_bounds__(256, 2) void attn_h(const __half* __restrict__ qkv,
                                                 __half* __restrict__ out) {
    extern __shared__ __half ash[];

    const int h  = blockIdx.x;
    const int qb = gridDim.y - 1 - blockIdx.y;
    const int kvh = h >> 2;
    const int tid = threadIdx.x;
    const int lane = tid & 31;
    const int wid = tid >> 5;
    const int q0 = wid * 16;
    const float qsc = 0.08838834764831845f * 1.4426950408889634f;

    const __half* kgbase = qkv + QSIZE + kvh * HD;
    const __half* vgbase = kgbase + KVSIZE;

    const uint32_t smBase = smem_u32(ash);
#define KV_ISSUE(j, s)                                                        \
    {                                                                         \
        const __half* kg_ = kgbase + (size_t)((j) * ABKV) * QKVW;             \
        const __half* vg_ = vgbase + (size_t)((j) * ABKV) * QKVW;             \
        uint32_t kb_ = smBase + (Q_HALVES + (s) * KV_STAGE_HALVES) * 2;       \
        uint32_t vb_ = kb_ + ABKV * QSH * 2;                                  \
        _Pragma("unroll")                                                     \
        for (int i_ = 0; i_ < 4; i_++) {                                      \
            int idx_ = i_ * 256 + tid;                                        \
            int r_ = idx_ >> 4, ck_ = (idx_ & 15) * 8;                        \
            uint32_t off_ = (r_ * QSH + ck_) * 2;                             \
            cpasync16(kb_ + off_, kg_ + (size_t)r_ * QKVW + ck_);             \
            cpasync16(vb_ + off_, vg_ + (size_t)r_ * QKVW + ck_);             \
        }                                                                     \
        asm volatile("cp.async.commit_group;");                               \
    }

    {
        const __half* qp = qkv + (size_t)(qb * ABQ) * QKVW + h * HD;
#pragma unroll
        for (int i = 0; i < 8; i++) {
            int idx = i * 256 + tid;
            int r = idx >> 4, ck = (idx & 15) * 8;
            cpasync16(smBase + (r * QSH + ck) * 2,
                      qp + (size_t)r * QKVW + ck);
        }
    }
    KV_ISSUE(0, 0);

    float m0 = -1e30f, m1 = -1e30f, l0 = 0.f, l1 = 0.f;
    float o[16][4];
#pragma unroll
    for (int ni = 0; ni < 16; ni++)
#pragma unroll
        for (int r = 0; r < 4; r++) o[ni][r] = 0.f;

    const uint32_t qA =
        smBase + ((q0 + (lane & 15)) * QSH + (lane >> 4) * 8) * 2;
    const uint32_t kOff =
        (((((lane >> 4) << 3) + (lane & 7)) * QSH + ((lane >> 3) & 1) * 8)) * 2;
    const uint32_t vOff = ((lane & 15) * QSH + ((lane >> 4) << 3)) * 2;

    const int rowg0 = qb * ABQ + q0;
    const int jmax = qb * 2 + 1;

    for (int j = 0; j <= jmax; j++) {
        asm volatile("cp.async.wait_group 0;");
        __syncthreads();
        if (j + 1 <= jmax) KV_ISSUE(j + 1, (j + 1) & 1);

        const uint32_t stBase =
            smBase + (Q_HALVES + (j & 1) * KV_STAGE_HALVES) * 2;
        const uint32_t kB = stBase + kOff;
        const uint32_t vB = stBase + ABKV * QSH * 2 + vOff;

        if (j * ABKV <= rowg0 + 15) {
            float sA[8][4];
#pragma unroll
            for (int ni = 0; ni < 8; ni++)
#pragma unroll
                for (int r = 0; r < 4; r++) sA[ni][r] = 0.f;

#pragma unroll
            for (int kc = 0; kc < 8; kc++) {
                uint32_t a[4];
                ldsm4(a[0], a[1], a[2], a[3], qA + kc * 32);
#pragma unroll
                for (int ng = 0; ng < 4; ng++) {
                    uint32_t b[4];
                    ldsm4(b[0], b[1], b[2], b[3],
                          kB + ng * (16 * QSH * 2) + kc * 32);
                    mma_f16(sA[ng * 2],     a[0], a[1], a[2], a[3], b[0], b[1]);
                    mma_f16(sA[ng * 2 + 1], a[0], a[1], a[2], a[3], b[2], b[3]);
                }
            }

#pragma unroll
            for (int ni = 0; ni < 8; ni++)
#pragma unroll
                for (int r = 0; r < 4; r++) sA[ni][r] *= qsc;

            if (j * ABKV + ABKV - 1 > rowg0) {
                int rg = rowg0 + (lane >> 2);
#pragma unroll
                for (int ni = 0; ni < 8; ni++) {
                    int c0 = j * ABKV + ni * 8 + (lane & 3) * 2;
                    if (c0     > rg)     sA[ni][0] = -INFINITY;
                    if (c0 + 1 > rg)     sA[ni][1] = -INFINITY;
                    if (c0     > rg + 8) sA[ni][2] = -INFINITY;
                    if (c0 + 1 > rg + 8) sA[ni][3] = -INFINITY;
                }
            }

            float mx0 = -INFINITY, mx1 = -INFINITY;
#pragma unroll
            for (int ni = 0; ni < 8; ni++) {
                mx0 = fmaxf(mx0, fmaxf(sA[ni][0], sA[ni][1]));
                mx1 = fmaxf(mx1, fmaxf(sA[ni][2], sA[ni][3]));
            }
            mx0 = fmaxf(mx0, __shfl_xor_sync(0xffffffffu, mx0, 1));
            mx0 = fmaxf(mx0, __shfl_xor_sync(0xffffffffu, mx0, 2));
            mx1 = fmaxf(mx1, __shfl_xor_sync(0xffffffffu, mx1, 1));
            mx1 = fmaxf(mx1, __shfl_xor_sync(0xffffffffu, mx1, 2));

            float mn0 = fmaxf(m0, mx0), mn1 = fmaxf(m1, mx1);
            float cr0 = exp2f(m0 - mn0), cr1 = exp2f(m1 - mn1);
            m0 = mn0; m1 = mn1;

            float s0 = 0.f, s1 = 0.f;
            uint32_t pF[4][4];
#pragma unroll
            for (int sk = 0; sk < 4; sk++) {
                float p00 = exp2f(sA[2 * sk][0] - mn0);
                float p01 = exp2f(sA[2 * sk][1] - mn0);
                float p02 = exp2f(sA[2 * sk][2] - mn1);
                float p03 = exp2f(sA[2 * sk][3] - mn1);
                float p10 = exp2f(sA[2 * sk + 1][0] - mn0);
                float p11 = exp2f(sA[2 * sk + 1][1] - mn0);
                float p12 = exp2f(sA[2 * sk + 1][2] - mn1);
                float p13 = exp2f(sA[2 * sk + 1][3] - mn1);
                s0 += p00 + p01 + p10 + p11;
                s1 += p02 + p03 + p12 + p13;
                pF[sk][0] = packh2(p00, p01);
                pF[sk][1] = packh2(p02, p03);
                pF[sk][2] = packh2(p10, p11);
                pF[sk][3] = packh2(p12, p13);
            }
            s0 += __shfl_xor_sync(0xffffffffu, s0, 1);
            s0 += __shfl_xor_sync(0xffffffffu, s0, 2);
            s1 += __shfl_xor_sync(0xffffffffu, s1, 1);
            s1 += __shfl_xor_sync(0xffffffffu, s1, 2);
            l0 = l0 * cr0 + s0;
            l1 = l1 * cr1 + s1;
#pragma unroll
            for (int ni = 0; ni < 16; ni++) {
                o[ni][0] *= cr0; o[ni][1] *= cr0;
                o[ni][2] *= cr1; o[ni][3] *= cr1;
            }

#pragma unroll
            for (int sk = 0; sk < 4; sk++) {
#pragma unroll
                for (int nb = 0; nb < 8; nb++) {
                    uint32_t v[4];
                    ldsm4t(v[0], v[1], v[2], v[3],
                           vB + sk * (16 * QSH * 2) + nb * 32);
                    mma_f16(o[nb * 2], pF[sk][0], pF[sk][1], pF[sk][2],
                            pF[sk][3], v[0], v[1]);
                    mma_f16(o[nb * 2 + 1], pF[sk][0], pF[sk][1], pF[sk][2],
                            pF[sk][3], v[2], v[3]);
                }
            }
        }
    }

    float i0 = 1.f / l0, i1 = 1.f / l1;
    int rg = qb * ABQ + q0 + (lane >> 2);
    __half* op = out + (size_t)rg * QSIZE + h * HD + (lane & 3) * 2;
#pragma unroll
    for (int ni = 0; ni < 16; ni++) {
        *(__half2*)(op + ni * 8) = __floats2half2_rn(o[ni][0] * i0, o[ni][1] * i0);
        *(__half2*)(op + (size_t)8 * QSIZE + ni * 8) =
            __floats2half2_rn(o[ni][2] * i1, o[ni][3] * i1);
    }
#undef KV_ISSUE
}

// ---------------------------------------------------------------------------
extern "C" void kernel_launch(void* const* d_in, const int* in_sizes, int n_in,
                              void* d_out, int out_size) {
    const int*   positions = (const int*)d_in[0];
    const float* hidden    = (const float*)d_in[1];
    const float* w_qkv     = (const float*)d_in[2];
    const float* w_o       = (const float*)d_in[3];
    float*       out       = (float*)d_out;

    void *qkv_p, *attn_p, *hid_p, *wqkvT_p, *woT_p;
    cudaGetSymbolAddress(&qkv_p, g_qkv16);
    cudaGetSymbolAddress(&attn_p, g_attn16);
    cudaGetSymbolAddress(&hid_p, g_hid16);
    cudaGetSymbolAddress(&wqkvT_p, g_wqkvT);
    cudaGetSymbolAddress(&woT_p, g_woT);
    __half* qkv16  = (__half*)qkv_p;
    __half* attn16 = (__half*)attn_p;
    __half* hid16  = (__half*)hid_p;
    __half* wqkvT  = (__half*)wqkvT_p;
    __half* woT    = (__half*)woT_p;

    cudaFuncSetAttribute(attn_h, cudaFuncAttributeMaxDynamicSharedMemorySize,
                         ATT_SMEM);
    cudaFuncSetAttribute(hgemm, cudaFuncAttributeMaxDynamicSharedMemorySize,
                         TG_SMEM);
    cudaFuncSetAttribute(hgemm_rope, cudaFuncAttributeMaxDynamicSharedMemorySize,
                         TG_SMEM);

    // 0) pre-passes: hidden -> half; weights -> transposed half [N][K]
    {
        int n4 = TT * HH / 4;
        conv_half<<<(n4 + 255) / 256, 256>>>(hidden, hid16, n4);
        dim3 tb(32, 8);
        transpose_half<<<dim3(QKVW / 32, HH / 32), tb>>>(w_qkv, wqkvT, HH, QKVW);
        transpose_half<<<dim3(HH / 32, QSIZE / 32), tb>>>(w_o, woT, QSIZE, HH);
    }
    // 1) qkv(half, rope applied) = hid @ w_qkv
    {
        dim3 grid(QKVW / BN, TT / BM);
        hgemm_rope<<<grid, 256, TG_SMEM>>>(hid16, wqkvT, qkv16, positions,
                                           TT, QKVW, HH);
    }
    // 2) attention (fp16 TC flash), half in/out
    {
        dim3 grid(NHEAD, TT / ABQ);
        attn_h<<<grid, 256, ATT_SMEM>>>(qkv16, attn16);
    }
    // 3) out = attn @ w_o  (fp16 TC, fp32 out)
    {
        dim3 grid(HH / BN, TT / BM);
        hgemm<<<grid, 256, TG_SMEM>>>(attn16, woT, out, TT, HH, QSIZE);
    }
}

// round 14
// speedup vs baseline: 1.4411x; 1.0079x over previous
#include <cuda_runtime.h>
#include <cuda_fp16.h>
#include <math.h>
#include <stdint.h>

// Problem constants
#define TT    2048
#define HH    4096
#define NHEAD 32
#define NKVH  8
#define HD    128
#define QSIZE 4096          // NHEAD*HD
#define KVSIZE 1024         // NKVH*HD
#define QKVW  6144          // QSIZE + 2*KVSIZE

// Scratch (no cudaMalloc allowed)
__device__ __half g_qkv16[(size_t)TT * QKVW];    // 24 MB (half qkv, rope applied)
__device__ __half g_attn16[(size_t)TT * QSIZE];  // 16 MB (half attn out)
__device__ __half g_hid16[(size_t)TT * HH];      // 16 MB (half hidden)
__device__ __half g_wqkvT[(size_t)QKVW * HH];    // 48 MB (w_qkv^T half)
__device__ __half g_woT[(size_t)HH * QSIZE];     // 32 MB (w_o^T half)

// ---------------------------------------------------------------------------
// Common helpers
// ---------------------------------------------------------------------------
__device__ __forceinline__ uint32_t smem_u32(const void* p) {
    return (uint32_t)__cvta_generic_to_shared(p);
}

__device__ __forceinline__ void ldsm4(uint32_t& r0, uint32_t& r1, uint32_t& r2,
                                      uint32_t& r3, uint32_t addr) {
    asm volatile("ldmatrix.sync.aligned.m8n8.x4.shared.b16 {%0,%1,%2,%3}, [%4];"
                 : "=r"(r0), "=r"(r1), "=r"(r2), "=r"(r3) : "r"(addr));
}

__device__ __forceinline__ void ldsm4t(uint32_t& r0, uint32_t& r1, uint32_t& r2,
                                       uint32_t& r3, uint32_t addr) {
    asm volatile(
        "ldmatrix.sync.aligned.m8n8.x4.trans.shared.b16 {%0,%1,%2,%3}, [%4];"
        : "=r"(r0), "=r"(r1), "=r"(r2), "=r"(r3) : "r"(addr));
}

__device__ __forceinline__ void mma_f16(float c[4], uint32_t a0, uint32_t a1,
                                        uint32_t a2, uint32_t a3,
                                        uint32_t b0, uint32_t b1) {
    asm volatile(
        "mma.sync.aligned.m16n8k16.row.col.f32.f16.f16.f32 "
        "{%0,%1,%2,%3}, {%4,%5,%6,%7}, {%8,%9}, {%0,%1,%2,%3};"
        : "+f"(c[0]), "+f"(c[1]), "+f"(c[2]), "+f"(c[3])
        : "r"(a0), "r"(a1), "r"(a2), "r"(a3), "r"(b0), "r"(b1));
}

__device__ __forceinline__ void cpasync16(uint32_t dst, const void* src) {
    asm volatile("cp.async.cg.shared.global [%0], [%1], 16;"
                 :: "r"(dst), "l"(src));
}

__device__ __forceinline__ uint32_t packh2(float a, float b) {
    __half2 h = __floats2half2_rn(a, b);
    return *(uint32_t*)&h;
}

__device__ __forceinline__ void mbar_init(uint32_t mbar, uint32_t cnt) {
    asm volatile("mbarrier.init.shared.b64 [%0], %1;" :: "r"(mbar), "r"(cnt)
                 : "memory");
}

__device__ __forceinline__ void mbar_arrive(uint32_t mbar) {
    asm volatile("mbarrier.arrive.shared.b64 _, [%0];" :: "r"(mbar) : "memory");
}

__device__ __forceinline__ void cp_arrive_noinc(uint32_t mbar) {
    asm volatile("cp.async.mbarrier.arrive.noinc.shared.b64 [%0];"
                 :: "r"(mbar) : "memory");
}

__device__ __forceinline__ void mbar_wait(uint32_t mbar, uint32_t phase) {
    asm volatile(
        "{\n\t.reg .pred P;\n"
        "W%=:\n\t"
        "mbarrier.try_wait.parity.acquire.cta.shared::cta.b64 P, [%0], %1, 0x989680;\n\t"
        "@P bra D%=;\n\t"
        "bra W%=;\n"
        "D%=:\n\t}"
        :: "r"(mbar), "r"(phase) : "memory");
}

// ---------------------------------------------------------------------------
// Pre-passes: fp32 -> half convert; fp32 [R][C] -> half [C][R] transpose
// ---------------------------------------------------------------------------
__global__ void conv_half(const float* __restrict__ in, __half* __restrict__ out,
                          int n4) {
    int i = blockIdx.x * blockDim.x + threadIdx.x;
    if (i >= n4) return;
    float4 v = ((const float4*)in)[i];
    __half2 h0 = __floats2half2_rn(v.x, v.y);
    __half2 h1 = __floats2half2_rn(v.z, v.w);
    ((uint2*)out)[i] = make_uint2(*(uint32_t*)&h0, *(uint32_t*)&h1);
}

__global__ void transpose_half(const float* __restrict__ in,
                               __half* __restrict__ out, int R, int C) {
    __shared__ float t[32][33];
    int tx = threadIdx.x, ty = threadIdx.y;
    int x = blockIdx.x * 32 + tx;
#pragma unroll
    for (int j = 0; j < 32; j += 8)
        t[ty + j][tx] = in[(size_t)(blockIdx.y * 32 + ty + j) * C + x];
    __syncthreads();
    int x2 = blockIdx.y * 32 + tx;
#pragma unroll
    for (int j = 0; j < 32; j += 8)
        out[(size_t)(blockIdx.x * 32 + ty + j) * R + x2] =
            __float2half_rn(t[tx][ty + j]);
}

// ---------------------------------------------------------------------------
// FP16 tensor-core GEMM, barrier-free elastic pipeline (mbarrier full/empty),
// with EARLY empty-arrive: stage released after last LDSM, before final MMAs.
// 128x128 CTA tile, 8 warps (2m x 4n), warp tile 64x32, BK=32 halves, 4 stages.
// ---------------------------------------------------------------------------
#define BM 128
#define BN 128
#define HAS 40
#define NST 4
#define STAGE_H (128 * HAS)
#define TG_SMEM (NST * 2 * STAGE_H * 2)
#define RGROUP 8

#define GEMM_PROLOGUE()                                                       \
    extern __shared__ __half smh[];                                           \
    __shared__ __align__(8) uint64_t s_full[NST];                             \
    __shared__ __align__(8) uint64_t s_empty[NST];                            \
    __half* As = smh;                                                         \
    __half* Bs = smh + NST * STAGE_H;                                         \
    const int tid  = threadIdx.x;                                             \
    const int lane = tid & 31;                                                \
    const int wid  = tid >> 5;                                                \
    const int mwarp = (wid >> 2) * 64;                                        \
    const int nwarp = (wid & 3) * 32;                                         \
    const int flat = blockIdx.y * gridDim.x + blockIdx.x;                     \
    const int strip = flat / (RGROUP * gridDim.y);                            \
    const int rem   = flat % (RGROUP * gridDim.y);                            \
    const int bx = strip * RGROUP + (rem % RGROUP);                           \
    const int by = rem / RGROUP;                                              \
    const int frow = tid >> 1;                                                \
    const int foff = (tid & 1) * 16;                                          \
    const __half* Ag = A + (size_t)(by * BM + frow) * K + foff;               \
    const __half* Bg = Bt + (size_t)(bx * BN + frow) * K + foff;              \
    const uint32_t aDst = smem_u32(&As[frow * HAS + foff]);                   \
    const uint32_t bDst = smem_u32(&Bs[frow * HAS + foff]);                   \
    const uint32_t mbF = smem_u32(s_full);                                    \
    const uint32_t mbE = smem_u32(s_empty);                                   \
    const int KT = K / 32;                                                    \
    if (tid == 0) {                                                           \
        for (int s_ = 0; s_ < NST; s_++) {                                    \
            mbar_init(mbF + s_ * 8, 256u);                                    \
            mbar_init(mbE + s_ * 8, 8u);                                      \
        }                                                                     \
    }                                                                         \
    __syncthreads();

#define ISSUE(kt, s)                                                          \
    {                                                                         \
        const __half* a_ = Ag + (kt) * 32;                                    \
        const __half* b_ = Bg + (kt) * 32;                                    \
        uint32_t ad_ = aDst + (s) * (STAGE_H * 2);                            \
        uint32_t bd_ = bDst + (s) * (STAGE_H * 2);                            \
        cpasync16(ad_, a_);                                                   \
        cpasync16(ad_ + 16, a_ + 8);                                          \
        cpasync16(bd_, b_);                                                   \
        cpasync16(bd_ + 16, b_ + 8);                                          \
        cp_arrive_noinc(mbF + (s) * 8);                                       \
    }

#define LOAD_FRAGS(aS, bS, ks, aF, bF)                                        \
    _Pragma("unroll")                                                         \
    for (int mi = 0; mi < 4; mi++)                                            \
        ldsm4(aF[mi][0], aF[mi][1], aF[mi][2], aF[mi][3],                     \
              (aS) + (mi * 16 * HAS + (ks) * 16) * 2);                        \
    _Pragma("unroll")                                                         \
    for (int ng = 0; ng < 2; ng++)                                            \
        ldsm4(bF[ng][0], bF[ng][1], bF[ng][2], bF[ng][3],                     \
              (bS) + (ng * 16 * HAS + (ks) * 16) * 2);

#define DO_MMAS(aF, bF)                                                       \
    _Pragma("unroll")                                                         \
    for (int mi = 0; mi < 4; mi++) {                                          \
        mma_f16(acc[mi][0], aF[mi][0], aF[mi][1], aF[mi][2], aF[mi][3],       \
                bF[0][0], bF[0][1]);                                          \
        mma_f16(acc[mi][1], aF[mi][0], aF[mi][1], aF[mi][2], aF[mi][3],       \
                bF[0][2], bF[0][3]);                                          \
        mma_f16(acc[mi][2], aF[mi][0], aF[mi][1], aF[mi][2], aF[mi][3],       \
                bF[1][0], bF[1][1]);                                          \
        mma_f16(acc[mi][3], aF[mi][0], aF[mi][1], aF[mi][2], aF[mi][3],       \
                bF[1][2], bF[1][3]);                                          \
    }

#define GEMM_MAINLOOP()                                                       \
    ISSUE(0, 0);                                                              \
    ISSUE(1, 1);                                                              \
    float acc[4][4][4];                                                       \
    _Pragma("unroll")                                                         \
    for (int mi = 0; mi < 4; mi++)                                            \
        _Pragma("unroll")                                                     \
        for (int ni = 0; ni < 4; ni++)                                        \
            _Pragma("unroll")                                                 \
            for (int r = 0; r < 4; r++) acc[mi][ni][r] = 0.f;                 \
    const uint32_t aAddr =                                                    \
        smem_u32(As) + ((mwarp + (lane & 15)) * HAS + (lane >> 4) * 8) * 2;   \
    const uint32_t bAddr =                                                    \
        smem_u32(Bs) +                                                        \
        ((nwarp + ((lane >> 4) << 3) + (lane & 7)) * HAS +                    \
         ((lane >> 3) & 1) * 8) * 2;                                          \
    for (int kt = 0; kt < KT; kt++) {                                         \
        const int fkt = kt + 2;                                               \
        if (fkt < KT) {                                                       \
            const int fs = fkt & (NST - 1);                                   \
            if (fkt >= NST)                                                   \
                mbar_wait(mbE + fs * 8, ((fkt >> 2) + 1) & 1);                \
            ISSUE(fkt, fs);                                                   \
        }                                                                     \
        const int s = kt & (NST - 1);                                         \
        mbar_wait(mbF + s * 8, (kt >> 2) & 1);                                \
        const uint32_t aS = aAddr + s * (STAGE_H * 2);                        \
        const uint32_t bS = bAddr + s * (STAGE_H * 2);                        \
        {                                                                     \
            uint32_t aF[4][4], bF[2][4];                                      \
            LOAD_FRAGS(aS, bS, 0, aF, bF);                                    \
            DO_MMAS(aF, bF);                                                  \
        }                                                                     \
        {                                                                     \
            uint32_t aF[4][4], bF[2][4];                                      \
            LOAD_FRAGS(aS, bS, 1, aF, bF);                                    \
            __syncwarp();                                                     \
            if (lane == 0) mbar_arrive(mbE + s * 8);  /* early release */     \
            DO_MMAS(aF, bF);                                                  \
        }                                                                     \
    }

// --- GEMM2: plain fp32 output ---------------------------------------------
__global__ __launch_bounds__(256, 2) void hgemm(const __half* __restrict__ A,
                                                const __half* __restrict__ Bt,
                                                float* __restrict__ C,
                                                int M, int N, int K) {
    GEMM_PROLOGUE();
    GEMM_MAINLOOP();
#pragma unroll
    for (int mi = 0; mi < 4; mi++) {
#pragma unroll
        for (int ni = 0; ni < 4; ni++) {
            int r = by * BM + mwarp + mi * 16 + (lane >> 2);
            int c = bx * BN + nwarp + ni * 8 + (lane & 3) * 2;
            *(float2*)&C[(size_t)r * N + c] =
                make_float2(acc[mi][ni][0], acc[mi][ni][1]);
            *(float2*)&C[(size_t)(r + 8) * N + c] =
                make_float2(acc[mi][ni][2], acc[mi][ni][3]);
        }
    }
}

// --- GEMM1: rope fused in epilogue, half output ----------------------------
__global__ __launch_bounds__(256, 2) void hgemm_rope(
    const __half* __restrict__ A, const __half* __restrict__ Bt,
    __half* __restrict__ Cq, const int* __restrict__ pos,
    int M, int N, int K) {
    GEMM_PROLOGUE();
    GEMM_MAINLOOP();

    if (bx < 40) {
        __syncthreads();      // all warps done with pipeline smem
        float* Cs = (float*)smh;
#pragma unroll
        for (int mi = 0; mi < 4; mi++) {
#pragma unroll
            for (int ni = 0; ni < 4; ni++) {
                int r = mwarp + mi * 16 + (lane >> 2);
                int c = nwarp + ni * 8 + (lane & 3) * 2;
                *(float2*)&Cs[r * 132 + c] =
                    make_float2(acc[mi][ni][0], acc[mi][ni][1]);
                *(float2*)&Cs[(r + 8) * 132 + c] =
                    make_float2(acc[mi][ni][2], acc[mi][ni][3]);
            }
        }
        __syncthreads();
        const int r = tid >> 1;
        const int ibase = (tid & 1) * 32;
        const int t = by * BM + r;
        const float pf = (float)pos[t];
        __half* dst = Cq + (size_t)t * QKVW + bx * BN;
#pragma unroll 8
        for (int ii = 0; ii < 32; ii += 2) {
            int i = ibase + ii;
            float inv0 = exp2f(-(float)i * 0.2958057710522857f);
            float inv1 = exp2f(-(float)(i + 1) * 0.2958057710522857f);
            float s0, c0, s1, c1;
            sincosf(pf * inv0, &s0, &c0);
            sincosf(pf * inv1, &s1, &c1);
            float x10 = Cs[r * 132 + i],     x20 = Cs[r * 132 + i + 64];
            float x11 = Cs[r * 132 + i + 1], x21 = Cs[r * 132 + i + 65];
            *(__half2*)(dst + i) =
                __floats2half2_rn(x10 * c0 - x20 * s0, x11 * c1 - x21 * s1);
            *(__half2*)(dst + i + 64) =
                __floats2half2_rn(x20 * c0 + x10 * s0, x21 * c1 + x11 * s1);
        }
    } else {
#pragma unroll
        for (int mi = 0; mi < 4; mi++) {
#pragma unroll
            for (int ni = 0; ni < 4; ni++) {
                int r = by * BM + mwarp + mi * 16 + (lane >> 2);
                int c = bx * BN + nwarp + ni * 8 + (lane & 3) * 2;
                *(__half2*)&Cq[(size_t)r * QKVW + c] =
                    __floats2half2_rn(acc[mi][ni][0], acc[mi][ni][1]);
                *(__half2*)&Cq[(size_t)(r + 8) * QKVW + c] =
                    __floats2half2_rn(acc[mi][ni][2], acc[mi][ni][3]);
            }
        }
    }
}

// ---------------------------------------------------------------------------
// FP16 flash attention (m16n8k16), causal, GQA group=4.
// R14: elastic mbarrier KV pipeline (full count 256 via cp.async noinc,
// empty count 8) replaces per-j wait_group+syncthreads. 2 stages.
// ---------------------------------------------------------------------------
#define ABQ  128
#define ABKV 64
#define QSH  136
#define Q_HALVES (ABQ * QSH)
#define KV_STAGE_HALVES (2 * ABKV * QSH)
#define ATT_SMEM ((Q_HALVES + 2 * KV_STAGE_HALVES) * 2)

__global__ __launch_bounds__(256, 2) void attn_h(const __half* __restrict__ qkv,
                                                 __half* __restrict__ out) {
    extern __shared__ __half ash[];
    __shared__ __align__(8) uint64_t a_full[2];
    __shared__ __align__(8) uint64_t a_empty[2];

    const int h  = blockIdx.x;
    const int qb = gridDim.y - 1 - blockIdx.y;
    const int kvh = h >> 2;
    const int tid = threadIdx.x;
    const int lane = tid & 31;
    const int wid = tid >> 5;
    const int q0 = wid * 16;
    const float qsc = 0.08838834764831845f * 1.4426950408889634f;

    const __half* kgbase = qkv + QSIZE + kvh * HD;
    const __half* vgbase = kgbase + KVSIZE;

    const uint32_t smBase = smem_u32(ash);
    const uint32_t mbF = smem_u32(a_full);
    const uint32_t mbE = smem_u32(a_empty);

    if (tid == 0) {
        mbar_init(mbF + 0, 256u);
        mbar_init(mbF + 8, 256u);
        mbar_init(mbE + 0, 8u);
        mbar_init(mbE + 8, 8u);
    }
    __syncthreads();

#define KV_ISSUE(j, s)                                                        \
    {                                                                         \
        const __half* kg_ = kgbase + (size_t)((j) * ABKV) * QKVW;             \
        const __half* vg_ = vgbase + (size_t)((j) * ABKV) * QKVW;             \
        uint32_t kb_ = smBase + (Q_HALVES + (s) * KV_STAGE_HALVES) * 2;       \
        uint32_t vb_ = kb_ + ABKV * QSH * 2;                                  \
        _Pragma("unroll")                                                     \
        for (int i_ = 0; i_ < 4; i_++) {                                      \
            int idx_ = i_ * 256 + tid;                                        \
            int r_ = idx_ >> 4, ck_ = (idx_ & 15) * 8;                        \
            uint32_t off_ = (r_ * QSH + ck_) * 2;                             \
            cpasync16(kb_ + off_, kg_ + (size_t)r_ * QKVW + ck_);             \
            cpasync16(vb_ + off_, vg_ + (size_t)r_ * QKVW + ck_);             \
        }                                                                     \
        cp_arrive_noinc(mbF + (s) * 8);                                       \
    }

    // prologue: Q copies + KV stage 0 (Q completion folded into full[0])
    {
        const __half* qp = qkv + (size_t)(qb * ABQ) * QKVW + h * HD;
#pragma unroll
        for (int i = 0; i < 8; i++) {
            int idx = i * 256 + tid;
            int r = idx >> 4, ck = (idx & 15) * 8;
            cpasync16(smBase + (r * QSH + ck) * 2,
                      qp + (size_t)r * QKVW + ck);
        }
    }
    KV_ISSUE(0, 0);

    float m0 = -1e30f, m1 = -1e30f, l0 = 0.f, l1 = 0.f;
    float o[16][4];
#pragma unroll
    for (int ni = 0; ni < 16; ni++)
#pragma unroll
        for (int r = 0; r < 4; r++) o[ni][r] = 0.f;

    const uint32_t qA =
        smBase + ((q0 + (lane & 15)) * QSH + (lane >> 4) * 8) * 2;
    const uint32_t kOff =
        (((((lane >> 4) << 3) + (lane & 7)) * QSH + ((lane >> 3) & 1) * 8)) * 2;
    const uint32_t vOff = ((lane & 15) * QSH + ((lane >> 4) << 3)) * 2;

    const int rowg0 = qb * ABQ + q0;
    const int jmax = qb * 2 + 1;

    for (int j = 0; j <= jmax; j++) {
        // prefetch next stage (gated on its empty if it's a reuse)
        const int fj = j + 1;
        if (fj <= jmax) {
            const int fs = fj & 1;
            if (fj >= 2) mbar_wait(mbE + fs * 8, ((fj >> 1) + 1) & 1);
            KV_ISSUE(fj, fs);
        }

        const int s = j & 1;
        mbar_wait(mbF + s * 8, (j >> 1) & 1);

        const uint32_t stBase =
            smBase + (Q_HALVES + s * KV_STAGE_HALVES) * 2;
        const uint32_t kB = stBase + kOff;
        const uint32_t vB = stBase + ABKV * QSH * 2 + vOff;

        if (j * ABKV <= rowg0 + 15) {
            float sA[8][4];
#pragma unroll
            for (int ni = 0; ni < 8; ni++)
#pragma unroll
                for (int r = 0; r < 4; r++) sA[ni][r] = 0.f;

#pragma unroll
            for (int kc = 0; kc < 8; kc++) {
                uint32_t a[4];
                ldsm4(a[0], a[1], a[2], a[3], qA + kc * 32);
#pragma unroll
                for (int ng = 0; ng < 4; ng++) {
                    uint32_t b[4];
                    ldsm4(b[0], b[1], b[2], b[3],
                          kB + ng * (16 * QSH * 2) + kc * 32);
                    mma_f16(sA[ng * 2],     a[0], a[1], a[2], a[3], b[0], b[1]);
                    mma_f16(sA[ng * 2 + 1], a[0], a[1], a[2], a[3], b[2], b[3]);
                }
            }

#pragma unroll
            for (int ni = 0; ni < 8; ni++)
#pragma unroll
                for (int r = 0; r < 4; r++) sA[ni][r] *= qsc;

            if (j * ABKV + ABKV - 1 > rowg0) {
                int rg = rowg0 + (lane >> 2);
#pragma unroll
                for (int ni = 0; ni < 8; ni++) {
                    int c0 = j * ABKV + ni * 8 + (lane & 3) * 2;
                    if (c0     > rg)     sA[ni][0] = -INFINITY;
                    if (c0 + 1 > rg)     sA[ni][1] = -INFINITY;
                    if (c0     > rg + 8) sA[ni][2] = -INFINITY;
                    if (c0 + 1 > rg + 8) sA[ni][3] = -INFINITY;
                }
            }

            float mx0 = -INFINITY, mx1 = -INFINITY;
#pragma unroll
            for (int ni = 0; ni < 8; ni++) {
                mx0 = fmaxf(mx0, fmaxf(sA[ni][0], sA[ni][1]));
                mx1 = fmaxf(mx1, fmaxf(sA[ni][2], sA[ni][3]));
            }
            mx0 = fmaxf(mx0, __shfl_xor_sync(0xffffffffu, mx0, 1));
            mx0 = fmaxf(mx0, __shfl_xor_sync(0xffffffffu, mx0, 2));
            mx1 = fmaxf(mx1, __shfl_xor_sync(0xffffffffu, mx1, 1));
            mx1 = fmaxf(mx1, __shfl_xor_sync(0xffffffffu, mx1, 2));

            float mn0 = fmaxf(m0, mx0), mn1 = fmaxf(m1, mx1);
            float cr0 = exp2f(m0 - mn0), cr1 = exp2f(m1 - mn1);
            m0 = mn0; m1 = mn1;

            float s0 = 0.f, s1 = 0.f;
            uint32_t pF[4][4];
#pragma unroll
            for (int sk = 0; sk < 4; sk++) {
                float p00 = exp2f(sA[2 * sk][0] - mn0);
                float p01 = exp2f(sA[2 * sk][1] - mn0);
                float p02 = exp2f(sA[2 * sk][2] - mn1);
                float p03 = exp2f(sA[2 * sk][3] - mn1);
                float p10 = exp2f(sA[2 * sk + 1][0] - mn0);
                float p11 = exp2f(sA[2 * sk + 1][1] - mn0);
                float p12 = exp2f(sA[2 * sk + 1][2] - mn1);
                float p13 = exp2f(sA[2 * sk + 1][3] - mn1);
                s0 += p00 + p01 + p10 + p11;
                s1 += p02 + p03 + p12 + p13;
                pF[sk][0] = packh2(p00, p01);
                pF[sk][1] = packh2(p02, p03);
                pF[sk][2] = packh2(p10, p11);
                pF[sk][3] = packh2(p12, p13);
            }
            s0 += __shfl_xor_sync(0xffffffffu, s0, 1);
            s0 += __shfl_xor_sync(0xffffffffu, s0, 2);
            s1 += __shfl_xor_sync(0xffffffffu, s1, 1);
            s1 += __shfl_xor_sync(0xffffffffu, s1, 2);
            l0 = l0 * cr0 + s0;
            l1 = l1 * cr1 + s1;
#pragma unroll
            for (int ni = 0; ni < 16; ni++) {
                o[ni][0] *= cr0; o[ni][1] *= cr0;
                o[ni][2] *= cr1; o[ni][3] *= cr1;
            }

#pragma unroll
            for (int sk = 0; sk < 4; sk++) {
#pragma unroll
                for (int nb = 0; nb < 8; nb++) {
                    uint32_t v[4];
                    ldsm4t(v[0], v[1], v[2], v[3],
                           vB + sk * (16 * QSH * 2) + nb * 32);
                    mma_f16(o[nb * 2], pF[sk][0], pF[sk][1], pF[sk][2],
                            pF[sk][3], v[0], v[1]);
                    mma_f16(o[nb * 2 + 1], pF[sk][0], pF[sk][1], pF[sk][2],
                            pF[sk][3], v[2], v[3]);
                }
            }
        }
        __syncwarp();
        if (lane == 0) mbar_arrive(mbE + s * 8);
    }

    float i0 = 1.f / l0, i1 = 1.f / l1;
    int rg = qb * ABQ + q0 + (lane >> 2);
    __half* op = out + (size_t)rg * QSIZE + h * HD + (lane & 3) * 2;
#pragma unroll
    for (int ni = 0; ni < 16; ni++) {
        *(__half2*)(op + ni * 8) = __floats2half2_rn(o[ni][0] * i0, o[ni][1] * i0);
        *(__half2*)(op + (size_t)8 * QSIZE + ni * 8) =
            __floats2half2_rn(o[ni][2] * i1, o[ni][3] * i1);
    }
#undef KV_ISSUE
}

// ---------------------------------------------------------------------------
extern "C" void kernel_launch(void* const* d_in, const int* in_sizes, int n_in,
                              void* d_out, int out_size) {
    const int*   positions = (const int*)d_in[0];
    const float* hidden    = (const float*)d_in[1];
    const float* w_qkv     = (const float*)d_in[2];
    const float* w_o       = (const float*)d_in[3];
    float*       out       = (float*)d_out;

    void *qkv_p, *attn_p, *hid_p, *wqkvT_p, *woT_p;
    cudaGetSymbolAddress(&qkv_p, g_qkv16);
    cudaGetSymbolAddress(&attn_p, g_attn16);
    cudaGetSymbolAddress(&hid_p, g_hid16);
    cudaGetSymbolAddress(&wqkvT_p, g_wqkvT);
    cudaGetSymbolAddress(&woT_p, g_woT);
    __half* qkv16  = (__half*)qkv_p;
    __half* attn16 = (__half*)attn_p;
    __half* hid16  = (__half*)hid_p;
    __half* wqkvT  = (__half*)wqkvT_p;
    __half* woT    = (__half*)woT_p;

    cudaFuncSetAttribute(attn_h, cudaFuncAttributeMaxDynamicSharedMemorySize,
                         ATT_SMEM);
    cudaFuncSetAttribute(hgemm, cudaFuncAttributeMaxDynamicSharedMemorySize,
                         TG_SMEM);
    cudaFuncSetAttribute(hgemm_rope, cudaFuncAttributeMaxDynamicSharedMemorySize,
                         TG_SMEM);

    // 0) pre-passes: hidden -> half; weights -> transposed half [N][K]
    {
        int n4 = TT * HH / 4;
        conv_half<<<(n4 + 255) / 256, 256>>>(hidden, hid16, n4);
        dim3 tb(32, 8);
        transpose_half<<<dim3(QKVW / 32, HH / 32), tb>>>(w_qkv, wqkvT, HH, QKVW);
        transpose_half<<<dim3(HH / 32, QSIZE / 32), tb>>>(w_o, woT, QSIZE, HH);
    }
    // 1) qkv(half, rope applied) = hid @ w_qkv
    {
        dim3 grid(QKVW / BN, TT / BM);
        hgemm_rope<<<grid, 256, TG_SMEM>>>(hid16, wqkvT, qkv16, positions,
                                           TT, QKVW, HH);
    }
    // 2) attention (fp16 TC flash), half in/out
    {
        dim3 grid(NHEAD, TT / ABQ);
        attn_h<<<grid, 256, ATT_SMEM>>>(qkv16, attn16);
    }
    // 3) out = attn @ w_o  (fp16 TC, fp32 out)
    {
        dim3 grid(HH / BN, TT / BM);
        hgemm<<<grid, 256, TG_SMEM>>>(attn16, woT, out, TT, HH, QSIZE);
    }
}